// round 1
// baseline (speedup 1.0000x reference)
#include <cuda_runtime.h>
#include <cstdint>
#include <math.h>

#define B_      8
#define M_      8
#define BM      64
#define SL      4096
#define P_      16
#define STRIDE_ 8
#define NP      511
#define DM      64
#define H_      8
#define DH      8
#define DFF     256
#define PRED    96
#define UP      35
#define NROW    (BM*NP)      // 32704
#define KTOT    (NP*DM)      // 32704
#define NSEG    32
#define SEG     1022         // 32*1022 = 32704

// ---------------- scratch ----------------
__device__ float g_z  [NROW*DM];
__device__ float g_q  [NROW*DM];
__device__ float g_k  [NROW*DM];
__device__ float g_v  [NROW*DM];
__device__ float g_ctx[NROW*DM];
__device__ float g_x1 [NROW*DM];
__device__ int   g_idx[NP*UP];
__device__ int   g_top[BM*H_*UP];
__device__ float g_pp [PRED*BM*NSEG];

// ---------------- threefry2x32 (bitwise JAX-compatible) ----------------
__device__ __forceinline__ uint32_t rotl32(uint32_t v, int r) {
    return (v << r) | (v >> (32 - r));
}

__device__ __forceinline__ void tf2x32(uint32_t k0, uint32_t k1,
                                       uint32_t& x0, uint32_t& x1) {
    uint32_t ks0 = k0, ks1 = k1, ks2 = k0 ^ k1 ^ 0x1BD11BDAu;
    const int ra[4] = {13, 15, 26, 6};
    const int rb[4] = {17, 29, 16, 24};
    x0 += ks0; x1 += ks1;
    #pragma unroll
    for (int i = 0; i < 4; i++) { x0 += x1; x1 = rotl32(x1, ra[i]); x1 ^= x0; }
    x0 += ks1; x1 += ks2 + 1u;
    #pragma unroll
    for (int i = 0; i < 4; i++) { x0 += x1; x1 = rotl32(x1, rb[i]); x1 ^= x0; }
    x0 += ks2; x1 += ks0 + 2u;
    #pragma unroll
    for (int i = 0; i < 4; i++) { x0 += x1; x1 = rotl32(x1, ra[i]); x1 ^= x0; }
    x0 += ks0; x1 += ks1 + 3u;
    #pragma unroll
    for (int i = 0; i < 4; i++) { x0 += x1; x1 = rotl32(x1, rb[i]); x1 ^= x0; }
    x0 += ks1; x1 += ks2 + 4u;
    #pragma unroll
    for (int i = 0; i < 4; i++) { x0 += x1; x1 = rotl32(x1, ra[i]); x1 ^= x0; }
    x0 += ks2; x1 += ks0 + 5u;
}

// random_bits over a size-17885 iota, odd-size zero padding (JAX threefry_2x32)
__device__ __forceinline__ uint32_t rbits17885(uint32_t k0, uint32_t k1, int j) {
    const int HALF = 8943;  // ceil(17885/2) after padding to 17886
    uint32_t x0, x1;
    if (j < HALF) {
        x0 = (uint32_t)j;
        x1 = (j < HALF - 1) ? (uint32_t)(j + HALF) : 0u;  // last lane pairs with pad 0
        tf2x32(k0, k1, x0, x1);
        return x0;
    } else {
        x0 = (uint32_t)(j - HALF);
        x1 = (uint32_t)j;
        tf2x32(k0, k1, x0, x1);
        return x1;
    }
}

__global__ void rand_idx_kernel(int e) {
    // folded key: threefry(key=(0,1), count=(0,e))
    uint32_t f0 = 0u, f1 = (uint32_t)e;
    tf2x32(0u, 1u, f0, f1);
    // split: counts iota(4) -> lane0 pair (0,2), lane1 pair (1,3)
    uint32_t a0 = 0u, a1 = 2u; tf2x32(f0, f1, a0, a1);   // (y0_0, y1_0)
    uint32_t b0 = 1u, b1 = 3u; tf2x32(f0, f1, b0, b1);   // (y0_1, y1_1)
    // k1 = (y0_0, y0_1), k2 = (y1_0, y1_1)
    uint32_t k1a = a0, k1b = b0;
    uint32_t k2a = a1, k2b = b1;

    int j = blockIdx.x * blockDim.x + threadIdx.x;
    if (j >= NP * UP) return;
    uint32_t hi = rbits17885(k1a, k1b, j);
    uint32_t lo = rbits17885(k2a, k2b, j);
    // randint: span=511, multiplier = (2^16 % 511)^2 % 511 = 32
    uint32_t off = ((hi % 511u) * 32u + (lo % 511u)) % 511u;
    g_idx[j] = (int)off;
}

// ---------------- patch embedding ----------------
// z[r][c] = sum_p x_enc[b, n*8+p, m] * in_W[c][p] + in_b[c];  r = bm*NP+n
__global__ void patch_embed_kernel(const float* __restrict__ xe,
                                   const float* __restrict__ inW,
                                   const float* __restrict__ inb) {
    __shared__ float ps[4][P_];
    int t = threadIdx.x;
    int r0 = blockIdx.x * 4;
    if (t < 64) {
        int rr = t / P_, p = t % P_;
        int r = r0 + rr;
        int bm = r / NP, n = r % NP;
        int b = bm / M_, m = bm % M_;
        ps[rr][p] = xe[(b * SL + n * STRIDE_ + p) * M_ + m];
    }
    __syncthreads();
    int rr = t / DM, c = t % DM;
    float acc = inb[c];
    #pragma unroll
    for (int p = 0; p < P_; p++) acc += inW[c * P_ + p] * ps[rr][p];
    g_z[(r0 + rr) * DM + c] = acc;
}

// ---------------- QKV projection ----------------
__global__ void qkv_kernel(const float* __restrict__ Wq, const float* __restrict__ bq,
                           const float* __restrict__ Wk, const float* __restrict__ bk,
                           const float* __restrict__ Wv, const float* __restrict__ bv) {
    const int TR = 32;
    __shared__ float zs[TR][DM];
    int t = threadIdx.x;
    int r0 = blockIdx.x * TR;
    for (int i = t; i < TR * DM; i += 256) zs[i / DM][i % DM] = g_z[r0 * DM + i];
    __syncthreads();
    int c = t % 64, g = t / 64;  // g in 0..3, rows g*8 .. g*8+7
    float acc[8];

    #pragma unroll
    for (int r = 0; r < 8; r++) acc[r] = bq[c];
    for (int k = 0; k < DM; k++) {
        float w = Wq[c * DM + k];
        #pragma unroll
        for (int r = 0; r < 8; r++) acc[r] += w * zs[g * 8 + r][k];
    }
    #pragma unroll
    for (int r = 0; r < 8; r++) g_q[(r0 + g * 8 + r) * DM + c] = acc[r];

    #pragma unroll
    for (int r = 0; r < 8; r++) acc[r] = bk[c];
    for (int k = 0; k < DM; k++) {
        float w = Wk[c * DM + k];
        #pragma unroll
        for (int r = 0; r < 8; r++) acc[r] += w * zs[g * 8 + r][k];
    }
    #pragma unroll
    for (int r = 0; r < 8; r++) g_k[(r0 + g * 8 + r) * DM + c] = acc[r];

    #pragma unroll
    for (int r = 0; r < 8; r++) acc[r] = bv[c];
    for (int k = 0; k < DM; k++) {
        float w = Wv[c * DM + k];
        #pragma unroll
        for (int r = 0; r < 8; r++) acc[r] += w * zs[g * 8 + r][k];
    }
    #pragma unroll
    for (int r = 0; r < 8; r++) g_v[(r0 + g * 8 + r) * DM + c] = acc[r];
}

// ---------------- sparsity sampling + top-k ----------------
__global__ void sample_topk_kernel() {
    int bm = blockIdx.x / H_, h = blockIdx.x % H_;
    __shared__ float ks[NP][DH];
    __shared__ float sp[NP];
    __shared__ float bv_[256];
    __shared__ int   bi_[256];
    int t = threadIdx.x;
    for (int i = t; i < NP * DH; i += 256) {
        int l = i / DH, d = i % DH;
        ks[l][d] = g_k[(bm * NP + l) * DM + h * DH + d];
    }
    __syncthreads();
    for (int l = t; l < NP; l += 256) {
        float q[8];
        #pragma unroll
        for (int d = 0; d < DH; d++) q[d] = g_q[(bm * NP + l) * DM + h * DH + d];
        float mx = -INFINITY, sm = 0.f;
        for (int u = 0; u < UP; u++) {
            int j = g_idx[l * UP + u];
            float dot = 0.f;
            #pragma unroll
            for (int d = 0; d < DH; d++) dot += q[d] * ks[j][d];
            mx = fmaxf(mx, dot);
            sm += dot;
        }
        sp[l] = mx - sm / (float)NP;
    }
    __syncthreads();
    // iterative arg-max 35 times, tie-break smallest index
    for (int it = 0; it < UP; it++) {
        float bv = -INFINITY; int bi = NP;
        for (int l = t; l < NP; l += 256) {
            float v = sp[l];
            if (v > bv || (v == bv && l < bi)) { bv = v; bi = l; }
        }
        bv_[t] = bv; bi_[t] = bi;
        __syncthreads();
        for (int s = 128; s > 0; s >>= 1) {
            if (t < s) {
                float v = bv_[t + s]; int i2 = bi_[t + s];
                if (v > bv_[t] || (v == bv_[t] && i2 < bi_[t])) { bv_[t] = v; bi_[t] = i2; }
            }
            __syncthreads();
        }
        if (t == 0) { g_top[blockIdx.x * UP + it] = bi_[0]; sp[bi_[0]] = -INFINITY; }
        __syncthreads();
    }
}

// ---------------- attention (mean ctx + dense rows for selected queries) ---
__global__ void attn_kernel() {
    int bm = blockIdx.x / H_, h = blockIdx.x % H_;
    __shared__ float ks[NP][DH];
    __shared__ float vs[NP][DH];
    __shared__ float vred[32][DH];
    int t = threadIdx.x, lane = t & 31, w = t >> 5;
    for (int i = t; i < NP * DH; i += 256) {
        int l = i / DH, d = i % DH;
        int base = (bm * NP + l) * DM + h * DH + d;
        ks[l][d] = g_k[base];
        vs[l][d] = g_v[base];
    }
    __syncthreads();
    // v mean over keys
    int d8 = t % DH;
    {
        float p = 0.f;
        for (int l = t / DH; l < NP; l += 32) p += vs[l][d8];
        vred[t / DH][d8] = p;
        __syncthreads();
        for (int s = 16; s >= 1; s >>= 1) {
            if (t < s * DH) vred[t / DH][d8] += vred[t / DH + s][d8];
            __syncthreads();
        }
    }
    float vm = vred[0][d8] / (float)NP;
    // broadcast mean to all ctx rows
    for (int l = t / DH; l < NP; l += 32)
        g_ctx[(bm * NP + l) * DM + h * DH + d8] = vm;
    __syncthreads();
    // dense attention for selected queries; warp w handles queries w, w+8, ...
    const float scale = 0.35355339059327373f;  // rsqrt(8)
    for (int i = w; i < UP; i += 8) {
        int l = g_top[blockIdx.x * UP + i];
        float q[8];
        #pragma unroll
        for (int d = 0; d < DH; d++) q[d] = g_q[(bm * NP + l) * DM + h * DH + d];
        float mx = -INFINITY;
        for (int j = lane; j < NP; j += 32) {
            float s = 0.f;
            #pragma unroll
            for (int d = 0; d < DH; d++) s += q[d] * ks[j][d];
            mx = fmaxf(mx, s * scale);
        }
        #pragma unroll
        for (int o = 16; o; o >>= 1) mx = fmaxf(mx, __shfl_xor_sync(0xffffffffu, mx, o));
        float sum = 0.f, acc[8] = {0.f, 0.f, 0.f, 0.f, 0.f, 0.f, 0.f, 0.f};
        for (int j = lane; j < NP; j += 32) {
            float s = 0.f;
            #pragma unroll
            for (int d = 0; d < DH; d++) s += q[d] * ks[j][d];
            float e = expf(s * scale - mx);
            sum += e;
            #pragma unroll
            for (int d = 0; d < DH; d++) acc[d] += e * vs[j][d];
        }
        #pragma unroll
        for (int o = 16; o; o >>= 1) {
            sum += __shfl_xor_sync(0xffffffffu, sum, o);
            #pragma unroll
            for (int d = 0; d < DH; d++) acc[d] += __shfl_xor_sync(0xffffffffu, acc[d], o);
        }
        if (lane == 0) {
            float inv = 1.f / sum;
            #pragma unroll
            for (int d = 0; d < DH; d++)
                g_ctx[(bm * NP + l) * DM + h * DH + d] = acc[d] * inv;
        }
    }
}

// ---------------- Wo + residual + LN1 ----------------
__global__ void wo_ln1_kernel(const float* __restrict__ Wo, const float* __restrict__ bo,
                              const float* __restrict__ g1, const float* __restrict__ b1) {
    const int TR = 16;
    __shared__ float cs[TR][DM];
    __shared__ float os[TR][DM];
    int t = threadIdx.x;
    int r0 = blockIdx.x * TR;
    for (int i = t; i < TR * DM; i += 256) cs[i / DM][i % DM] = g_ctx[r0 * DM + i];
    __syncthreads();
    int c = t % 64, g = t / 64;  // rows g*4..g*4+3
    float acc[4];
    #pragma unroll
    for (int r = 0; r < 4; r++) acc[r] = bo[c];
    for (int k = 0; k < DM; k++) {
        float w = Wo[c * DM + k];
        #pragma unroll
        for (int r = 0; r < 4; r++) acc[r] += w * cs[g * 4 + r][k];
    }
    #pragma unroll
    for (int r = 0; r < 4; r++)
        os[g * 4 + r][c] = acc[r] + g_z[(r0 + g * 4 + r) * DM + c];
    __syncthreads();
    int lane = t & 31, w2 = t >> 5;
    for (int rr = w2 * 2; rr < w2 * 2 + 2; rr++) {
        float v0 = os[rr][lane], v1 = os[rr][lane + 32];
        float s = v0 + v1;
        #pragma unroll
        for (int o = 16; o; o >>= 1) s += __shfl_xor_sync(0xffffffffu, s, o);
        float mu = s / 64.f;
        float d0 = v0 - mu, d1 = v1 - mu;
        float vv = d0 * d0 + d1 * d1;
        #pragma unroll
        for (int o = 16; o; o >>= 1) vv += __shfl_xor_sync(0xffffffffu, vv, o);
        float inv = 1.f / sqrtf(vv / 64.f + 1e-5f);
        g_x1[(r0 + rr) * DM + lane]      = d0 * inv * g1[lane]      + b1[lane];
        g_x1[(r0 + rr) * DM + lane + 32] = d1 * inv * g1[lane + 32] + b1[lane + 32];
    }
}

// ---------------- FFN (c1 -> GELU -> c2) + residual + LN2 -> z -------------
__global__ void ffn_ln2_kernel(const float* __restrict__ W1, const float* __restrict__ b1f,
                               const float* __restrict__ W2, const float* __restrict__ b2f,
                               const float* __restrict__ g2, const float* __restrict__ bb2) {
    const int TR = 16;
    __shared__ float xs[TR][DM];       // 4 KB
    __shared__ float ys[DFF][TR];      // 16 KB
    __shared__ float os[TR][DM];       // 4 KB
    int t = threadIdx.x;
    int r0 = blockIdx.x * TR;
    for (int i = t; i < TR * DM; i += 256) xs[i / DM][i % DM] = g_x1[r0 * DM + i];
    __syncthreads();
    // c1 + GELU: thread t owns DFF output channel t
    {
        float acc[TR];
        #pragma unroll
        for (int r = 0; r < TR; r++) acc[r] = b1f[t];
        for (int k = 0; k < DM; k++) {
            float w = W1[t * DM + k];
            #pragma unroll
            for (int r = 0; r < TR; r++) acc[r] += w * xs[r][k];
        }
        #pragma unroll
        for (int r = 0; r < TR; r++) {
            float x = acc[r];
            ys[t][r] = x * 0.5f * (1.f + erff(x * 0.7071067811865476f));
        }
    }
    __syncthreads();
    // c2: thread -> (out col j = t%64, rows g*4..g*4+3)
    {
        int j = t % 64, g = t / 64;
        float acc[4];
        #pragma unroll
        for (int r = 0; r < 4; r++) acc[r] = b2f[j];
        for (int k = 0; k < DFF; k++) {
            float w = W2[j * DFF + k];
            #pragma unroll
            for (int r = 0; r < 4; r++) acc[r] += w * ys[k][g * 4 + r];
        }
        #pragma unroll
        for (int r = 0; r < 4; r++)
            os[g * 4 + r][j] = acc[r] + xs[g * 4 + r][j];
    }
    __syncthreads();
    int lane = t & 31, w2 = t >> 5;
    for (int rr = w2 * 2; rr < w2 * 2 + 2; rr++) {
        float v0 = os[rr][lane], v1 = os[rr][lane + 32];
        float s = v0 + v1;
        #pragma unroll
        for (int o = 16; o; o >>= 1) s += __shfl_xor_sync(0xffffffffu, s, o);
        float mu = s / 64.f;
        float d0 = v0 - mu, d1 = v1 - mu;
        float vv = d0 * d0 + d1 * d1;
        #pragma unroll
        for (int o = 16; o; o >>= 1) vv += __shfl_xor_sync(0xffffffffu, vv, o);
        float inv = 1.f / sqrtf(vv / 64.f + 1e-5f);
        g_z[(r0 + rr) * DM + lane]      = d0 * inv * g2[lane]      + bb2[lane];
        g_z[(r0 + rr) * DM + lane + 32] = d1 * inv * g2[lane + 32] + bb2[lane + 32];
    }
}

// ---------------- final LN (in place on g_z) ----------------
__global__ void final_ln_kernel(const float* __restrict__ gf, const float* __restrict__ bf) {
    int t = threadIdx.x, lane = t & 31, w = t >> 5;
    int r = blockIdx.x * 8 + w;
    float v0 = g_z[r * DM + lane], v1 = g_z[r * DM + lane + 32];
    float s = v0 + v1;
    #pragma unroll
    for (int o = 16; o; o >>= 1) s += __shfl_xor_sync(0xffffffffu, s, o);
    float mu = s / 64.f;
    float d0 = v0 - mu, d1 = v1 - mu;
    float vv = d0 * d0 + d1 * d1;
    #pragma unroll
    for (int o = 16; o; o >>= 1) vv += __shfl_xor_sync(0xffffffffu, vv, o);
    float inv = 1.f / sqrtf(vv / 64.f + 1e-5f);
    g_z[r * DM + lane]      = d0 * inv * gf[lane]      + bf[lane];
    g_z[r * DM + lane + 32] = d1 * inv * gf[lane + 32] + bf[lane + 32];
}

// ---------------- output projection (two-stage, deterministic) -------------
__global__ void proj_partial_kernel(const float* __restrict__ outW) {
    int seg = blockIdx.x;    // 0..31
    int bg  = blockIdx.y;    // 0..7 -> bm = bg*8 .. bg*8+7
    __shared__ float zc[8][SEG];   // ~32 KB
    int t = threadIdx.x, lane = t & 31, w = t >> 5;
    int k0 = seg * SEG;
    for (int i = t; i < 8 * SEG; i += 256) {
        int bmo = i / SEG, kk = i % SEG;
        zc[bmo][kk] = g_z[(bg * 8 + bmo) * KTOT + k0 + kk];
    }
    __syncthreads();
    for (int p = w; p < PRED; p += 8) {
        float acc[8] = {0.f, 0.f, 0.f, 0.f, 0.f, 0.f, 0.f, 0.f};
        for (int kk = lane; kk < SEG; kk += 32) {
            float ww = outW[p * KTOT + k0 + kk];
            #pragma unroll
            for (int bmo = 0; bmo < 8; bmo++) acc[bmo] += ww * zc[bmo][kk];
        }
        #pragma unroll
        for (int bmo = 0; bmo < 8; bmo++) {
            #pragma unroll
            for (int o = 16; o; o >>= 1)
                acc[bmo] += __shfl_xor_sync(0xffffffffu, acc[bmo], o);
        }
        if (lane == 0) {
            #pragma unroll
            for (int bmo = 0; bmo < 8; bmo++)
                g_pp[(p * BM + bg * 8 + bmo) * NSEG + seg] = acc[bmo];
        }
    }
}

__global__ void proj_reduce_kernel(const float* __restrict__ outb, float* __restrict__ out) {
    int i = blockIdx.x * 256 + threadIdx.x;
    if (i >= PRED * BM) return;
    int p = i / BM, bm = i % BM;
    float s = outb[p];
    #pragma unroll
    for (int seg = 0; seg < NSEG; seg++) s += g_pp[(p * BM + bm) * NSEG + seg];
    int b = bm / M_, m = bm % M_;
    out[(b * PRED + p) * M_ + m] = s;   // (B, PRED, M)
}

// ---------------- launch ----------------
extern "C" void kernel_launch(void* const* d_in, const int* in_sizes, int n_in,
                              void* d_out, int out_size) {
    const float* x_enc = (const float*)d_in[0];
    const float* in_W  = (const float*)d_in[4];
    const float* in_b  = (const float*)d_in[5];
    const float* Wq    = (const float*)d_in[6];
    const float* bq    = (const float*)d_in[7];
    const float* Wk    = (const float*)d_in[8];
    const float* bk    = (const float*)d_in[9];
    const float* Wv    = (const float*)d_in[10];
    const float* bv    = (const float*)d_in[11];
    const float* Wo    = (const float*)d_in[12];
    const float* bo    = (const float*)d_in[13];
    const float* c1_W  = (const float*)d_in[14];
    const float* c1_b  = (const float*)d_in[15];
    const float* c2_W  = (const float*)d_in[16];
    const float* c2_b  = (const float*)d_in[17];
    const float* ln1_g = (const float*)d_in[18];
    const float* ln1_b = (const float*)d_in[19];
    const float* ln2_g = (const float*)d_in[20];
    const float* ln2_b = (const float*)d_in[21];
    const float* lnf_g = (const float*)d_in[22];
    const float* lnf_b = (const float*)d_in[23];
    const float* out_W = (const float*)d_in[24];
    const float* out_b = (const float*)d_in[25];
    float* out = (float*)d_out;

    patch_embed_kernel<<<NROW / 4, 256>>>(x_enc, in_W, in_b);

    for (int e = 0; e < 2; e++) {
        rand_idx_kernel<<<(NP * UP + 255) / 256, 256>>>(e);
        qkv_kernel<<<NROW / 32, 256>>>(Wq + e * DM * DM, bq + e * DM,
                                       Wk + e * DM * DM, bk + e * DM,
                                       Wv + e * DM * DM, bv + e * DM);
        sample_topk_kernel<<<BM * H_, 256>>>();
        attn_kernel<<<BM * H_, 256>>>();
        wo_ln1_kernel<<<NROW / 16, 256>>>(Wo + e * DM * DM, bo + e * DM,
                                          ln1_g + e * DM, ln1_b + e * DM);
        ffn_ln2_kernel<<<NROW / 16, 256>>>(c1_W + e * DFF * DM, c1_b + e * DFF,
                                           c2_W + e * DM * DFF, c2_b + e * DM,
                                           ln2_g + e * DM, ln2_b + e * DM);
    }

    final_ln_kernel<<<NROW / 8, 256>>>(lnf_g, lnf_b);
    proj_partial_kernel<<<dim3(NSEG, 8), 256>>>(out_W);
    proj_reduce_kernel<<<(PRED * BM + 255) / 256, 256>>>(out_b, out);
}

// round 3
// speedup vs baseline: 6.8491x; 6.8491x over previous
#include <cuda_runtime.h>
#include <cstdint>
#include <math.h>

#define B_      8
#define M_      8
#define BM      64
#define SL      4096
#define P_      16
#define STRIDE_ 8
#define NP      511
#define DM      64
#define H_      8
#define DH      8
#define DFF     256
#define PRED    96
#define UP      35
#define NROW    (BM*NP)      // 32704
#define KTOT    (NP*DM)      // 32704
#define NSEG    32
#define SEG     1022

// ---------------- scratch ----------------
__device__ float g_z  [NROW*DM];
__device__ float g_q  [NROW*DM];
__device__ float g_k  [NROW*DM];
__device__ float g_v  [NROW*DM];
__device__ float g_ctx[NROW*DM];
__device__ float g_x1 [NROW*DM];
__device__ int   g_idx[NP*UP];
__device__ float g_pp [PRED*BM*NSEG];

__device__ __forceinline__ void fma4(float4& o, float s, const float4& b) {
    o.x += s * b.x; o.y += s * b.y; o.z += s * b.z; o.w += s * b.w;
}

// ---------------- threefry2x32 (bitwise JAX-compatible) ----------------
__device__ __forceinline__ uint32_t rotl32(uint32_t v, int r) {
    return (v << r) | (v >> (32 - r));
}

__device__ __forceinline__ void tf2x32(uint32_t k0, uint32_t k1,
                                       uint32_t& x0, uint32_t& x1) {
    uint32_t ks0 = k0, ks1 = k1, ks2 = k0 ^ k1 ^ 0x1BD11BDAu;
    const int ra[4] = {13, 15, 26, 6};
    const int rb[4] = {17, 29, 16, 24};
    x0 += ks0; x1 += ks1;
    #pragma unroll
    for (int i = 0; i < 4; i++) { x0 += x1; x1 = rotl32(x1, ra[i]); x1 ^= x0; }
    x0 += ks1; x1 += ks2 + 1u;
    #pragma unroll
    for (int i = 0; i < 4; i++) { x0 += x1; x1 = rotl32(x1, rb[i]); x1 ^= x0; }
    x0 += ks2; x1 += ks0 + 2u;
    #pragma unroll
    for (int i = 0; i < 4; i++) { x0 += x1; x1 = rotl32(x1, ra[i]); x1 ^= x0; }
    x0 += ks0; x1 += ks1 + 3u;
    #pragma unroll
    for (int i = 0; i < 4; i++) { x0 += x1; x1 = rotl32(x1, rb[i]); x1 ^= x0; }
    x0 += ks1; x1 += ks2 + 4u;
    #pragma unroll
    for (int i = 0; i < 4; i++) { x0 += x1; x1 = rotl32(x1, ra[i]); x1 ^= x0; }
    x0 += ks2; x1 += ks0 + 5u;
}

__device__ __forceinline__ uint32_t rbits17885(uint32_t k0, uint32_t k1, int j) {
    const int HALF = 8943;
    uint32_t x0, x1;
    if (j < HALF) {
        x0 = (uint32_t)j;
        x1 = (j < HALF - 1) ? (uint32_t)(j + HALF) : 0u;
        tf2x32(k0, k1, x0, x1);
        return x0;
    } else {
        x0 = (uint32_t)(j - HALF);
        x1 = (uint32_t)j;
        tf2x32(k0, k1, x0, x1);
        return x1;
    }
}

__global__ void rand_idx_kernel(int e) {
    uint32_t f0 = 0u, f1 = (uint32_t)e;
    tf2x32(0u, 1u, f0, f1);
    uint32_t a0 = 0u, a1 = 2u; tf2x32(f0, f1, a0, a1);
    uint32_t b0 = 1u, b1 = 3u; tf2x32(f0, f1, b0, b1);
    int j = blockIdx.x * blockDim.x + threadIdx.x;
    if (j >= NP * UP) return;
    uint32_t hi = rbits17885(a0, b0, j);
    uint32_t lo = rbits17885(a1, b1, j);
    uint32_t off = ((hi % 511u) * 32u + (lo % 511u)) % 511u;
    g_idx[j] = (int)off;
}

// ---------------- patch embedding ----------------
__global__ void patch_embed_kernel(const float* __restrict__ xe,
                                   const float* __restrict__ inW,
                                   const float* __restrict__ inb) {
    __shared__ float ps[16][17];
    __shared__ float ws[64][17];
    __shared__ float bs[64];
    int t = threadIdx.x;
    int r0 = blockIdx.x * 16;
    {
        int rr = t / 16, p = t % 16;
        int r = r0 + rr;
        int bm = r / NP, n = r % NP;
        int b = bm / M_, m = bm % M_;
        ps[rr][p] = xe[(b * SL + n * STRIDE_ + p) * M_ + m];
    }
    for (int i = t; i < 64 * P_; i += 256) ws[i / P_][i % P_] = inW[i];
    if (t < 64) bs[t] = inb[t];
    __syncthreads();
    int c = t % 64, q4 = t / 64;
    #pragma unroll
    for (int rr = q4 * 4; rr < q4 * 4 + 4; rr++) {
        float acc = bs[c];
        #pragma unroll
        for (int p = 0; p < P_; p++) acc += ws[c][p] * ps[rr][p];
        g_z[(r0 + rr) * DM + c] = acc;
    }
}

// ---------------- QKV GEMM: 128-row x 64-col tile, 8x4 per thread ----------
struct SmemG128 {
    float As[128][68];
    float Bs[64][68];
};

__global__ __launch_bounds__(256)
void qkv_kernel(const float* __restrict__ Wq, const float* __restrict__ bq,
                const float* __restrict__ Wk, const float* __restrict__ bk,
                const float* __restrict__ Wv, const float* __restrict__ bv) {
    extern __shared__ char smem_raw[];
    SmemG128* S = (SmemG128*)smem_raw;
    int t = threadIdx.x;
    int r0 = blockIdx.x * 128;
    int rows = NROW - r0; if (rows > 128) rows = 128;
    const float* W; const float* bias; float* out;
    if (blockIdx.y == 0)      { W = Wq; bias = bq; out = g_q; }
    else if (blockIdx.y == 1) { W = Wk; bias = bk; out = g_k; }
    else                      { W = Wv; bias = bv; out = g_v; }

    for (int i = t; i < 128 * 16; i += 256) {
        int row = i / 16, f4 = i % 16;
        float4 v = make_float4(0.f, 0.f, 0.f, 0.f);
        if (row < rows) v = *(const float4*)&g_z[(r0 + row) * DM + f4 * 4];
        *(float4*)&S->As[row][f4 * 4] = v;
    }
    {
        int c = t >> 2, ks0 = (t & 3) * 16;
        #pragma unroll
        for (int q = 0; q < 4; q++) {
            float4 wv = *(const float4*)&W[c * 64 + ks0 + q * 4];
            S->Bs[ks0 + q * 4 + 0][c] = wv.x;
            S->Bs[ks0 + q * 4 + 1][c] = wv.y;
            S->Bs[ks0 + q * 4 + 2][c] = wv.z;
            S->Bs[ks0 + q * 4 + 3][c] = wv.w;
        }
    }
    __syncthreads();
    int rg = t >> 4, cg = t & 15;
    float4 acc[8];
    #pragma unroll
    for (int r = 0; r < 8; r++) acc[r] = make_float4(0.f, 0.f, 0.f, 0.f);
    #pragma unroll
    for (int k = 0; k < 64; k += 4) {
        float4 b0 = *(float4*)&S->Bs[k + 0][cg * 4];
        float4 b1 = *(float4*)&S->Bs[k + 1][cg * 4];
        float4 b2 = *(float4*)&S->Bs[k + 2][cg * 4];
        float4 b3 = *(float4*)&S->Bs[k + 3][cg * 4];
        #pragma unroll
        for (int r = 0; r < 8; r++) {
            float4 a = *(float4*)&S->As[rg * 8 + r][k];
            fma4(acc[r], a.x, b0); fma4(acc[r], a.y, b1);
            fma4(acc[r], a.z, b2); fma4(acc[r], a.w, b3);
        }
    }
    float4 bb = *(const float4*)&bias[cg * 4];
    #pragma unroll
    for (int r = 0; r < 8; r++) {
        int row = rg * 8 + r;
        if (row < rows) {
            float4 o = make_float4(acc[r].x + bb.x, acc[r].y + bb.y,
                                   acc[r].z + bb.z, acc[r].w + bb.w);
            *(float4*)&out[(r0 + row) * DM + cg * 4] = o;
        }
    }
}

// ---------------- fused sparsity + topk + attention ----------------
__global__ __launch_bounds__(256)
void attn_kernel() {
    __shared__ float ks[NP][8];
    __shared__ float vs[NP][8];
    __shared__ float sp[512];
    __shared__ float vpart[28][8];
    __shared__ float vm[8];
    __shared__ int   top[UP];
    int bm = blockIdx.x / H_, h = blockIdx.x % H_;
    int t = threadIdx.x, lane = t & 31, w = t >> 5;
    long rbase = (long)bm * NP;

    const float4* gk4 = (const float4*)g_k;
    const float4* gv4 = (const float4*)g_v;
    const float4* gq4 = (const float4*)g_q;
    for (int i = t; i < NP * 2; i += 256) {
        int l = i >> 1, half = i & 1;
        long src = (rbase + l) * 16 + h * 2 + half;
        ((float4*)ks)[i] = gk4[src];
        ((float4*)vs)[i] = gv4[src];
    }
    __syncthreads();

    for (int l = t; l < NP; l += 256) {
        long qb = (rbase + l) * 16 + h * 2;
        float4 q0 = gq4[qb], q1 = gq4[qb + 1];
        float mx = -INFINITY, sm = 0.f;
        for (int u = 0; u < UP; u++) {
            int j = g_idx[l * UP + u];
            float4 k0 = *(float4*)&ks[j][0];
            float4 k1 = *(float4*)&ks[j][4];
            float dot = q0.x*k0.x + q0.y*k0.y + q0.z*k0.z + q0.w*k0.w
                      + q1.x*k1.x + q1.y*k1.y + q1.z*k1.z + q1.w*k1.w;
            mx = fmaxf(mx, dot);
            sm += dot;
        }
        sp[l] = mx - sm / (float)NP;
    }
    __syncthreads();

    if (w == 0) {
        float vals[16];
        #pragma unroll
        for (int jj = 0; jj < 16; jj++) {
            int l = lane + 32 * jj;
            vals[jj] = (l < NP) ? sp[l] : -INFINITY;
        }
        for (int it = 0; it < UP; it++) {
            float bv = -INFINITY; int bi = NP;
            #pragma unroll
            for (int jj = 0; jj < 16; jj++) {
                int l = lane + 32 * jj;
                float v = vals[jj];
                if (v > bv) { bv = v; bi = l; }
            }
            #pragma unroll
            for (int off = 16; off; off >>= 1) {
                float ov = __shfl_xor_sync(0xffffffffu, bv, off);
                int   oi = __shfl_xor_sync(0xffffffffu, bi, off);
                if (ov > bv || (ov == bv && oi < bi)) { bv = ov; bi = oi; }
            }
            if (lane == 0) top[it] = bi;
            int tgt = bi >> 5;
            if ((bi & 31) == lane) {
                #pragma unroll
                for (int jj = 0; jj < 16; jj++)
                    if (jj == tgt) vals[jj] = -INFINITY;
            }
        }
    } else {
        int d = (t - 32) & 7, slice = (t - 32) >> 3;
        float s = 0.f;
        for (int l = slice; l < NP; l += 28) s += vs[l][d];
        vpart[slice][d] = s;
    }
    __syncthreads();
    if (t < 8) {
        float s = 0.f;
        #pragma unroll
        for (int i = 0; i < 28; i++) s += vpart[i][t];
        vm[t] = s / (float)NP;
    }
    __syncthreads();

    float4* gc4 = (float4*)g_ctx;
    {
        float4 m0 = *(float4*)&vm[0];
        float4 m1 = *(float4*)&vm[4];
        for (int i = t; i < NP * 2; i += 256) {
            int l = i >> 1, half = i & 1;
            gc4[(rbase + l) * 16 + h * 2 + half] = (half == 0) ? m0 : m1;
        }
    }
    __syncthreads();

    const float scale = 0.35355339059327373f;
    for (int i = w; i < UP; i += 8) {
        int l = top[i];
        long qb = (rbase + l) * 16 + h * 2;
        float4 q0 = gq4[qb], q1 = gq4[qb + 1];
        float s[16];
        #pragma unroll
        for (int jj = 0; jj < 16; jj++) {
            int j = lane + 32 * jj;
            if (j < NP) {
                float4 k0 = *(float4*)&ks[j][0];
                float4 k1 = *(float4*)&ks[j][4];
                s[jj] = (q0.x*k0.x + q0.y*k0.y + q0.z*k0.z + q0.w*k0.w
                       + q1.x*k1.x + q1.y*k1.y + q1.z*k1.z + q1.w*k1.w) * scale;
            } else s[jj] = -INFINITY;
        }
        float mx = -INFINITY;
        #pragma unroll
        for (int jj = 0; jj < 16; jj++) mx = fmaxf(mx, s[jj]);
        #pragma unroll
        for (int off = 16; off; off >>= 1)
            mx = fmaxf(mx, __shfl_xor_sync(0xffffffffu, mx, off));
        float sum = 0.f;
        float4 a0 = make_float4(0.f, 0.f, 0.f, 0.f);
        float4 a1 = make_float4(0.f, 0.f, 0.f, 0.f);
        #pragma unroll
        for (int jj = 0; jj < 16; jj++) {
            int j = lane + 32 * jj;
            if (j < NP) {
                float e = expf(s[jj] - mx);
                sum += e;
                float4 v0 = *(float4*)&vs[j][0];
                float4 v1 = *(float4*)&vs[j][4];
                fma4(a0, e, v0); fma4(a1, e, v1);
            }
        }
        #pragma unroll
        for (int off = 16; off; off >>= 1) {
            sum  += __shfl_xor_sync(0xffffffffu, sum, off);
            a0.x += __shfl_xor_sync(0xffffffffu, a0.x, off);
            a0.y += __shfl_xor_sync(0xffffffffu, a0.y, off);
            a0.z += __shfl_xor_sync(0xffffffffu, a0.z, off);
            a0.w += __shfl_xor_sync(0xffffffffu, a0.w, off);
            a1.x += __shfl_xor_sync(0xffffffffu, a1.x, off);
            a1.y += __shfl_xor_sync(0xffffffffu, a1.y, off);
            a1.z += __shfl_xor_sync(0xffffffffu, a1.z, off);
            a1.w += __shfl_xor_sync(0xffffffffu, a1.w, off);
        }
        if (lane == 0) {
            float inv = 1.f / sum;
            float4 o0 = make_float4(a0.x*inv, a0.y*inv, a0.z*inv, a0.w*inv);
            float4 o1 = make_float4(a1.x*inv, a1.y*inv, a1.z*inv, a1.w*inv);
            gc4[qb]     = o0;
            gc4[qb + 1] = o1;
        }
    }
}

// ---------------- Wo GEMM + residual + LN1 ----------------
__global__ __launch_bounds__(256)
void wo_ln1_kernel(const float* __restrict__ Wo, const float* __restrict__ bo,
                   const float* __restrict__ g1, const float* __restrict__ b1) {
    extern __shared__ char smem_raw[];
    SmemG128* S = (SmemG128*)smem_raw;
    int t = threadIdx.x;
    int r0 = blockIdx.x * 128;
    int rows = NROW - r0; if (rows > 128) rows = 128;

    for (int i = t; i < 128 * 16; i += 256) {
        int row = i / 16, f4 = i % 16;
        float4 v = make_float4(0.f, 0.f, 0.f, 0.f);
        if (row < rows) v = *(const float4*)&g_ctx[(r0 + row) * DM + f4 * 4];
        *(float4*)&S->As[row][f4 * 4] = v;
    }
    {
        int c = t >> 2, ks0 = (t & 3) * 16;
        #pragma unroll
        for (int q = 0; q < 4; q++) {
            float4 wv = *(const float4*)&Wo[c * 64 + ks0 + q * 4];
            S->Bs[ks0 + q * 4 + 0][c] = wv.x;
            S->Bs[ks0 + q * 4 + 1][c] = wv.y;
            S->Bs[ks0 + q * 4 + 2][c] = wv.z;
            S->Bs[ks0 + q * 4 + 3][c] = wv.w;
        }
    }
    __syncthreads();
    int rg = t >> 4, cg = t & 15;
    float4 acc[8];
    #pragma unroll
    for (int r = 0; r < 8; r++) acc[r] = make_float4(0.f, 0.f, 0.f, 0.f);
    #pragma unroll
    for (int k = 0; k < 64; k += 4) {
        float4 b0 = *(float4*)&S->Bs[k + 0][cg * 4];
        float4 b1v = *(float4*)&S->Bs[k + 1][cg * 4];
        float4 b2 = *(float4*)&S->Bs[k + 2][cg * 4];
        float4 b3 = *(float4*)&S->Bs[k + 3][cg * 4];
        #pragma unroll
        for (int r = 0; r < 8; r++) {
            float4 a = *(float4*)&S->As[rg * 8 + r][k];
            fma4(acc[r], a.x, b0); fma4(acc[r], a.y, b1v);
            fma4(acc[r], a.z, b2); fma4(acc[r], a.w, b3);
        }
    }
    __syncthreads();
    float4 bb = *(const float4*)&bo[cg * 4];
    #pragma unroll
    for (int r = 0; r < 8; r++) {
        int row = rg * 8 + r;
        if (row < rows) {
            float4 z = *(const float4*)&g_z[(r0 + row) * DM + cg * 4];
            S->As[row][cg * 4 + 0] = acc[r].x + bb.x + z.x;
            S->As[row][cg * 4 + 1] = acc[r].y + bb.y + z.y;
            S->As[row][cg * 4 + 2] = acc[r].z + bb.z + z.z;
            S->As[row][cg * 4 + 3] = acc[r].w + bb.w + z.w;
        }
    }
    __syncthreads();
    int lane = t & 31, w2 = t >> 5;
    for (int rr = 0; rr < 16; rr++) {
        int row = w2 * 16 + rr;
        if (row >= rows) break;
        float v0 = S->As[row][lane], v1 = S->As[row][lane + 32];
        float s = v0 + v1;
        #pragma unroll
        for (int o = 16; o; o >>= 1) s += __shfl_xor_sync(0xffffffffu, s, o);
        float mu = s / 64.f;
        float d0 = v0 - mu, d1 = v1 - mu;
        float vv = d0 * d0 + d1 * d1;
        #pragma unroll
        for (int o = 16; o; o >>= 1) vv += __shfl_xor_sync(0xffffffffu, vv, o);
        float inv = rsqrtf(vv / 64.f + 1e-5f);
        g_x1[(r0 + row) * DM + lane]      = d0 * inv * g1[lane]      + b1[lane];
        g_x1[(r0 + row) * DM + lane + 32] = d1 * inv * g1[lane + 32] + b1[lane + 32];
    }
}

// ---------------- fused FFN + residual + LN2 (64 rows/block) --------------
struct SmemFFN {
    float xs[64][68];
    float wb[64][68];
    float ys[64][260];
};

__global__ __launch_bounds__(256)
void ffn_ln2_kernel(const float* __restrict__ W1, const float* __restrict__ b1f,
                    const float* __restrict__ W2, const float* __restrict__ b2f,
                    const float* __restrict__ g2, const float* __restrict__ bb2) {
    extern __shared__ char smem_raw[];
    SmemFFN* S = (SmemFFN*)smem_raw;
    int t = threadIdx.x;
    int r0 = blockIdx.x * 64;
    int rg = t >> 4, cg = t & 15;
    int cw = t >> 2, ks0 = (t & 3) * 16;

    for (int i = t; i < 64 * 16; i += 256) {
        int row = i / 16, f4 = i % 16;
        *(float4*)&S->xs[row][f4 * 4] = *(const float4*)&g_x1[(r0 + row) * DM + f4 * 4];
    }

    for (int cc = 0; cc < 4; cc++) {
        __syncthreads();
        #pragma unroll
        for (int q = 0; q < 4; q++) {
            float4 wv = *(const float4*)&W1[(cc * 64 + cw) * 64 + ks0 + q * 4];
            S->wb[ks0 + q * 4 + 0][cw] = wv.x;
            S->wb[ks0 + q * 4 + 1][cw] = wv.y;
            S->wb[ks0 + q * 4 + 2][cw] = wv.z;
            S->wb[ks0 + q * 4 + 3][cw] = wv.w;
        }
        __syncthreads();
        float4 acc[4];
        #pragma unroll
        for (int r = 0; r < 4; r++) acc[r] = make_float4(0.f, 0.f, 0.f, 0.f);
        #pragma unroll
        for (int k = 0; k < 64; k += 4) {
            float4 b0 = *(float4*)&S->wb[k + 0][cg * 4];
            float4 b1 = *(float4*)&S->wb[k + 1][cg * 4];
            float4 b2 = *(float4*)&S->wb[k + 2][cg * 4];
            float4 b3 = *(float4*)&S->wb[k + 3][cg * 4];
            #pragma unroll
            for (int r = 0; r < 4; r++) {
                float4 a = *(float4*)&S->xs[rg * 4 + r][k];
                fma4(acc[r], a.x, b0); fma4(acc[r], a.y, b1);
                fma4(acc[r], a.z, b2); fma4(acc[r], a.w, b3);
            }
        }
        float4 bb = *(const float4*)&b1f[cc * 64 + cg * 4];
        #pragma unroll
        for (int r = 0; r < 4; r++) {
            float x0 = acc[r].x + bb.x, x1 = acc[r].y + bb.y;
            float x2 = acc[r].z + bb.z, x3 = acc[r].w + bb.w;
            float4 y;
            y.x = x0 * 0.5f * (1.f + erff(x0 * 0.7071067811865476f));
            y.y = x1 * 0.5f * (1.f + erff(x1 * 0.7071067811865476f));
            y.z = x2 * 0.5f * (1.f + erff(x2 * 0.7071067811865476f));
            y.w = x3 * 0.5f * (1.f + erff(x3 * 0.7071067811865476f));
            *(float4*)&S->ys[rg * 4 + r][cc * 64 + cg * 4] = y;
        }
    }

    float4 acc2[4];
    #pragma unroll
    for (int r = 0; r < 4; r++) acc2[r] = make_float4(0.f, 0.f, 0.f, 0.f);
    for (int kc = 0; kc < 4; kc++) {
        __syncthreads();
        #pragma unroll
        for (int q = 0; q < 4; q++) {
            float4 wv = *(const float4*)&W2[cw * 256 + kc * 64 + ks0 + q * 4];
            S->wb[ks0 + q * 4 + 0][cw] = wv.x;
            S->wb[ks0 + q * 4 + 1][cw] = wv.y;
            S->wb[ks0 + q * 4 + 2][cw] = wv.z;
            S->wb[ks0 + q * 4 + 3][cw] = wv.w;
        }
        __syncthreads();
        #pragma unroll
        for (int k = 0; k < 64; k += 4) {
            float4 b0 = *(float4*)&S->wb[k + 0][cg * 4];
            float4 b1 = *(float4*)&S->wb[k + 1][cg * 4];
            float4 b2 = *(float4*)&S->wb[k + 2][cg * 4];
            float4 b3 = *(float4*)&S->wb[k + 3][cg * 4];
            #pragma unroll
            for (int r = 0; r < 4; r++) {
                float4 a = *(float4*)&S->ys[rg * 4 + r][kc * 64 + k];
                fma4(acc2[r], a.x, b0); fma4(acc2[r], a.y, b1);
                fma4(acc2[r], a.z, b2); fma4(acc2[r], a.w, b3);
            }
        }
    }
    __syncthreads();
    {
        float4 bb = *(const float4*)&b2f[cg * 4];
        #pragma unroll
        for (int r = 0; r < 4; r++) {
            int row = rg * 4 + r;
            S->xs[row][cg * 4 + 0] += acc2[r].x + bb.x;
            S->xs[row][cg * 4 + 1] += acc2[r].y + bb.y;
            S->xs[row][cg * 4 + 2] += acc2[r].z + bb.z;
            S->xs[row][cg * 4 + 3] += acc2[r].w + bb.w;
        }
    }
    __syncthreads();
    int lane = t & 31, w2 = t >> 5;
    #pragma unroll
    for (int rr = 0; rr < 8; rr++) {
        int row = w2 * 8 + rr;
        float v0 = S->xs[row][lane], v1 = S->xs[row][lane + 32];
        float s = v0 + v1;
        #pragma unroll
        for (int o = 16; o; o >>= 1) s += __shfl_xor_sync(0xffffffffu, s, o);
        float mu = s / 64.f;
        float d0 = v0 - mu, d1 = v1 - mu;
        float vv = d0 * d0 + d1 * d1;
        #pragma unroll
        for (int o = 16; o; o >>= 1) vv += __shfl_xor_sync(0xffffffffu, vv, o);
        float inv = rsqrtf(vv / 64.f + 1e-5f);
        g_z[(r0 + row) * DM + lane]      = d0 * inv * g2[lane]      + bb2[lane];
        g_z[(r0 + row) * DM + lane + 32] = d1 * inv * g2[lane + 32] + bb2[lane + 32];
    }
}

// ---------------- final LN ----------------
__global__ void final_ln_kernel(const float* __restrict__ gf, const float* __restrict__ bf) {
    int t = threadIdx.x, lane = t & 31, w = t >> 5;
    int r = blockIdx.x * 8 + w;
    float v0 = g_z[r * DM + lane], v1 = g_z[r * DM + lane + 32];
    float s = v0 + v1;
    #pragma unroll
    for (int o = 16; o; o >>= 1) s += __shfl_xor_sync(0xffffffffu, s, o);
    float mu = s / 64.f;
    float d0 = v0 - mu, d1 = v1 - mu;
    float vv = d0 * d0 + d1 * d1;
    #pragma unroll
    for (int o = 16; o; o >>= 1) vv += __shfl_xor_sync(0xffffffffu, vv, o);
    float inv = rsqrtf(vv / 64.f + 1e-5f);
    g_z[r * DM + lane]      = d0 * inv * gf[lane]      + bf[lane];
    g_z[r * DM + lane + 32] = d1 * inv * gf[lane + 32] + bf[lane + 32];
}

// ---------------- output projection ----------------
__global__ void proj_partial_kernel(const float* __restrict__ outW) {
    int seg = blockIdx.x;
    int bg  = blockIdx.y;
    __shared__ float zc[8][SEG];
    int t = threadIdx.x, lane = t & 31, w = t >> 5;
    int k0 = seg * SEG;
    for (int i = t; i < 8 * SEG; i += 256) {
        int bmo = i / SEG, kk = i % SEG;
        zc[bmo][kk] = g_z[(bg * 8 + bmo) * KTOT + k0 + kk];
    }
    __syncthreads();
    for (int p = w; p < PRED; p += 8) {
        float acc[8] = {0.f, 0.f, 0.f, 0.f, 0.f, 0.f, 0.f, 0.f};
        for (int kk = lane; kk < SEG; kk += 32) {
            float ww = outW[p * KTOT + k0 + kk];
            #pragma unroll
            for (int bmo = 0; bmo < 8; bmo++) acc[bmo] += ww * zc[bmo][kk];
        }
        #pragma unroll
        for (int bmo = 0; bmo < 8; bmo++) {
            #pragma unroll
            for (int o = 16; o; o >>= 1)
                acc[bmo] += __shfl_xor_sync(0xffffffffu, acc[bmo], o);
        }
        if (lane == 0) {
            #pragma unroll
            for (int bmo = 0; bmo < 8; bmo++)
                g_pp[(p * BM + bg * 8 + bmo) * NSEG + seg] = acc[bmo];
        }
    }
}

__global__ void proj_reduce_kernel(const float* __restrict__ outb, float* __restrict__ out) {
    int i = blockIdx.x * 256 + threadIdx.x;
    if (i >= PRED * BM) return;
    int p = i / BM, bm = i % BM;
    float s = outb[p];
    #pragma unroll
    for (int seg = 0; seg < NSEG; seg++) s += g_pp[(p * BM + bm) * NSEG + seg];
    int b = bm / M_, m = bm % M_;
    out[(b * PRED + p) * M_ + m] = s;
}

// ---------------- launch ----------------
extern "C" void kernel_launch(void* const* d_in, const int* in_sizes, int n_in,
                              void* d_out, int out_size) {
    const float* x_enc = (const float*)d_in[0];
    const float* in_W  = (const float*)d_in[4];
    const float* in_b  = (const float*)d_in[5];
    const float* Wq    = (const float*)d_in[6];
    const float* bq    = (const float*)d_in[7];
    const float* Wk    = (const float*)d_in[8];
    const float* bk    = (const float*)d_in[9];
    const float* Wv    = (const float*)d_in[10];
    const float* bv    = (const float*)d_in[11];
    const float* Wo    = (const float*)d_in[12];
    const float* bo    = (const float*)d_in[13];
    const float* c1_W  = (const float*)d_in[14];
    const float* c1_b  = (const float*)d_in[15];
    const float* c2_W  = (const float*)d_in[16];
    const float* c2_b  = (const float*)d_in[17];
    const float* ln1_g = (const float*)d_in[18];
    const float* ln1_b = (const float*)d_in[19];
    const float* ln2_g = (const float*)d_in[20];
    const float* ln2_b = (const float*)d_in[21];
    const float* lnf_g = (const float*)d_in[22];
    const float* lnf_b = (const float*)d_in[23];
    const float* out_W = (const float*)d_in[24];
    const float* out_b = (const float*)d_in[25];
    float* out = (float*)d_out;

    const int smemG = sizeof(SmemG128);
    const int smemF = sizeof(SmemFFN);
    cudaFuncSetAttribute(qkv_kernel,    cudaFuncAttributeMaxDynamicSharedMemorySize, smemG);
    cudaFuncSetAttribute(wo_ln1_kernel, cudaFuncAttributeMaxDynamicSharedMemorySize, smemG);
    cudaFuncSetAttribute(ffn_ln2_kernel,cudaFuncAttributeMaxDynamicSharedMemorySize, smemF);

    patch_embed_kernel<<<NROW / 16, 256>>>(x_enc, in_W, in_b);

    for (int e = 0; e < 2; e++) {
        rand_idx_kernel<<<(NP * UP + 255) / 256, 256>>>(e);
        qkv_kernel<<<dim3(256, 3), 256, smemG>>>(Wq + e * DM * DM, bq + e * DM,
                                                 Wk + e * DM * DM, bk + e * DM,
                                                 Wv + e * DM * DM, bv + e * DM);
        attn_kernel<<<BM * H_, 256>>>();
        wo_ln1_kernel<<<256, 256, smemG>>>(Wo + e * DM * DM, bo + e * DM,
                                           ln1_g + e * DM, ln1_b + e * DM);
        ffn_ln2_kernel<<<NROW / 64, 256, smemF>>>(c1_W + e * DFF * DM, c1_b + e * DFF,
                                                  c2_W + e * DM * DFF, c2_b + e * DM,
                                                  ln2_g + e * DM, ln2_b + e * DM);
    }

    final_ln_kernel<<<NROW / 8, 256>>>(lnf_g, lnf_b);
    proj_partial_kernel<<<dim3(NSEG, 8), 256>>>(out_W);
    proj_reduce_kernel<<<(PRED * BM + 255) / 256, 256>>>(out_b, out);
}

// round 4
// speedup vs baseline: 7.4585x; 1.0890x over previous
#include <cuda_runtime.h>
#include <cstdint>
#include <math.h>

#define B_      8
#define M_      8
#define BM      64
#define SL      4096
#define P_      16
#define STRIDE_ 8
#define NP      511
#define DM      64
#define H_      8
#define DH      8
#define DFF     256
#define PRED    96
#define UP      35
#define NROW    (BM*NP)      // 32704
#define KTOT    (NP*DM)      // 32704
#define NSEG    32
#define SEG     1022

// ---------------- scratch ----------------
__device__ float g_z  [NROW*DM];
__device__ float g_q  [NROW*DM];
__device__ float g_k  [NROW*DM];
__device__ float g_v  [NROW*DM];
__device__ float g_ctx[NROW*DM];
__device__ float g_x1 [NROW*DM];
__device__ int   g_idx[NP*UP];
__device__ int   g_top[BM*H_*UP];
__device__ float g_vmean[BM*DM];
__device__ float g_pp [PRED*BM*NSEG];

__device__ __forceinline__ void fma4(float4& o, float s, const float4& b) {
    o.x += s * b.x; o.y += s * b.y; o.z += s * b.z; o.w += s * b.w;
}

// ---------------- threefry2x32 (bitwise JAX-compatible) ----------------
__device__ __forceinline__ uint32_t rotl32(uint32_t v, int r) {
    return (v << r) | (v >> (32 - r));
}

__device__ __forceinline__ void tf2x32(uint32_t k0, uint32_t k1,
                                       uint32_t& x0, uint32_t& x1) {
    uint32_t ks0 = k0, ks1 = k1, ks2 = k0 ^ k1 ^ 0x1BD11BDAu;
    const int ra[4] = {13, 15, 26, 6};
    const int rb[4] = {17, 29, 16, 24};
    x0 += ks0; x1 += ks1;
    #pragma unroll
    for (int i = 0; i < 4; i++) { x0 += x1; x1 = rotl32(x1, ra[i]); x1 ^= x0; }
    x0 += ks1; x1 += ks2 + 1u;
    #pragma unroll
    for (int i = 0; i < 4; i++) { x0 += x1; x1 = rotl32(x1, rb[i]); x1 ^= x0; }
    x0 += ks2; x1 += ks0 + 2u;
    #pragma unroll
    for (int i = 0; i < 4; i++) { x0 += x1; x1 = rotl32(x1, ra[i]); x1 ^= x0; }
    x0 += ks0; x1 += ks1 + 3u;
    #pragma unroll
    for (int i = 0; i < 4; i++) { x0 += x1; x1 = rotl32(x1, rb[i]); x1 ^= x0; }
    x0 += ks1; x1 += ks2 + 4u;
    #pragma unroll
    for (int i = 0; i < 4; i++) { x0 += x1; x1 = rotl32(x1, ra[i]); x1 ^= x0; }
    x0 += ks2; x1 += ks0 + 5u;
}

__device__ __forceinline__ uint32_t rbits17885(uint32_t k0, uint32_t k1, int j) {
    const int HALF = 8943;
    uint32_t x0, x1;
    if (j < HALF) {
        x0 = (uint32_t)j;
        x1 = (j < HALF - 1) ? (uint32_t)(j + HALF) : 0u;
        tf2x32(k0, k1, x0, x1);
        return x0;
    } else {
        x0 = (uint32_t)(j - HALF);
        x1 = (uint32_t)j;
        tf2x32(k0, k1, x0, x1);
        return x1;
    }
}

__global__ void rand_idx_kernel(int e) {
    uint32_t f0 = 0u, f1 = (uint32_t)e;
    tf2x32(0u, 1u, f0, f1);
    uint32_t a0 = 0u, a1 = 2u; tf2x32(f0, f1, a0, a1);
    uint32_t b0 = 1u, b1 = 3u; tf2x32(f0, f1, b0, b1);
    int j = blockIdx.x * blockDim.x + threadIdx.x;
    if (j >= NP * UP) return;
    uint32_t hi = rbits17885(a0, b0, j);
    uint32_t lo = rbits17885(a1, b1, j);
    uint32_t off = ((hi % 511u) * 32u + (lo % 511u)) % 511u;
    g_idx[j] = (int)off;
}

// ---------------- patch embedding ----------------
__global__ void patch_embed_kernel(const float* __restrict__ xe,
                                   const float* __restrict__ inW,
                                   const float* __restrict__ inb) {
    __shared__ float ps[16][17];
    __shared__ float ws[64][17];
    __shared__ float bs[64];
    int t = threadIdx.x;
    int r0 = blockIdx.x * 16;
    {
        int rr = t / 16, p = t % 16;
        int r = r0 + rr;
        int bm = r / NP, n = r % NP;
        int b = bm / M_, m = bm % M_;
        ps[rr][p] = xe[(b * SL + n * STRIDE_ + p) * M_ + m];
    }
    for (int i = t; i < 64 * P_; i += 256) ws[i / P_][i % P_] = inW[i];
    if (t < 64) bs[t] = inb[t];
    __syncthreads();
    int c = t % 64, q4 = t / 64;
    #pragma unroll
    for (int rr = q4 * 4; rr < q4 * 4 + 4; rr++) {
        float acc = bs[c];
        #pragma unroll
        for (int p = 0; p < P_; p++) acc += ws[c][p] * ps[rr][p];
        g_z[(r0 + rr) * DM + c] = acc;
    }
}

// ---------------- QKV GEMM ----------------
struct SmemG128 {
    float As[128][68];
    float Bs[64][68];
};

__global__ __launch_bounds__(256)
void qkv_kernel(const float* __restrict__ Wq, const float* __restrict__ bq,
                const float* __restrict__ Wk, const float* __restrict__ bk,
                const float* __restrict__ Wv, const float* __restrict__ bv) {
    extern __shared__ char smem_raw[];
    SmemG128* S = (SmemG128*)smem_raw;
    int t = threadIdx.x;
    int r0 = blockIdx.x * 128;
    int rows = NROW - r0; if (rows > 128) rows = 128;
    const float* W; const float* bias; float* out;
    if (blockIdx.y == 0)      { W = Wq; bias = bq; out = g_q; }
    else if (blockIdx.y == 1) { W = Wk; bias = bk; out = g_k; }
    else                      { W = Wv; bias = bv; out = g_v; }

    for (int i = t; i < 128 * 16; i += 256) {
        int row = i / 16, f4 = i % 16;
        float4 v = make_float4(0.f, 0.f, 0.f, 0.f);
        if (row < rows) v = *(const float4*)&g_z[(r0 + row) * DM + f4 * 4];
        *(float4*)&S->As[row][f4 * 4] = v;
    }
    {
        int c = t >> 2, ks0 = (t & 3) * 16;
        #pragma unroll
        for (int q = 0; q < 4; q++) {
            float4 wv = *(const float4*)&W[c * 64 + ks0 + q * 4];
            S->Bs[ks0 + q * 4 + 0][c] = wv.x;
            S->Bs[ks0 + q * 4 + 1][c] = wv.y;
            S->Bs[ks0 + q * 4 + 2][c] = wv.z;
            S->Bs[ks0 + q * 4 + 3][c] = wv.w;
        }
    }
    __syncthreads();
    int rg = t >> 4, cg = t & 15;
    float4 acc[8];
    #pragma unroll
    for (int r = 0; r < 8; r++) acc[r] = make_float4(0.f, 0.f, 0.f, 0.f);
    #pragma unroll
    for (int k = 0; k < 64; k += 4) {
        float4 b0 = *(float4*)&S->Bs[k + 0][cg * 4];
        float4 b1 = *(float4*)&S->Bs[k + 1][cg * 4];
        float4 b2 = *(float4*)&S->Bs[k + 2][cg * 4];
        float4 b3 = *(float4*)&S->Bs[k + 3][cg * 4];
        #pragma unroll
        for (int r = 0; r < 8; r++) {
            float4 a = *(float4*)&S->As[rg * 8 + r][k];
            fma4(acc[r], a.x, b0); fma4(acc[r], a.y, b1);
            fma4(acc[r], a.z, b2); fma4(acc[r], a.w, b3);
        }
    }
    float4 bb = *(const float4*)&bias[cg * 4];
    #pragma unroll
    for (int r = 0; r < 8; r++) {
        int row = rg * 8 + r;
        if (row < rows) {
            float4 o = make_float4(acc[r].x + bb.x, acc[r].y + bb.y,
                                   acc[r].z + bb.z, acc[r].w + bb.w);
            *(float4*)&out[(r0 + row) * DM + cg * 4] = o;
        }
    }
}

// ---------------- V mean per bm ----------------
__global__ __launch_bounds__(256)
void vmean_kernel() {
    __shared__ float part[4][64];
    int bm = blockIdx.x;
    int t = threadIdx.x;
    int col = t & 63, slice = t >> 6;
    float s = 0.f;
    for (int l = slice; l < NP; l += 4) s += g_v[(bm * NP + l) * DM + col];
    part[slice][col] = s;
    __syncthreads();
    if (t < 64) {
        float v = (part[0][t] + part[1][t] + part[2][t] + part[3][t]) / (float)NP;
        g_vmean[bm * DM + t] = v;
    }
}

// ---------------- broadcast vmean into g_ctx ----------------
__global__ __launch_bounds__(256)
void bcast_kernel() {
    int i = blockIdx.x * 256 + threadIdx.x;   // NROW*16 float4s, exact multiple
    int row = i >> 4, f4 = i & 15;
    int bm = row / NP;
    ((float4*)g_ctx)[i] = ((const float4*)g_vmean)[bm * 16 + f4];
}

// ---------------- sparsity + top-k ----------------
__global__ __launch_bounds__(256)
void topk_kernel() {
    __shared__ float ks[NP][8];
    __shared__ float sp[512];
    int bm = blockIdx.x / H_, h = blockIdx.x % H_;
    int t = threadIdx.x, lane = t & 31, w = t >> 5;
    long rbase = (long)bm * NP;

    const float4* gk4 = (const float4*)g_k;
    const float4* gq4 = (const float4*)g_q;
    for (int i = t; i < NP * 2; i += 256) {
        int l = i >> 1, half = i & 1;
        ((float4*)ks)[i] = gk4[(rbase + l) * 16 + h * 2 + half];
    }
    __syncthreads();

    for (int l = t; l < NP; l += 256) {
        long qb = (rbase + l) * 16 + h * 2;
        float4 q0 = gq4[qb], q1 = gq4[qb + 1];
        float mx = -INFINITY, sm = 0.f;
        #pragma unroll 7
        for (int u = 0; u < UP; u++) {
            int j = g_idx[l * UP + u];
            float4 k0 = *(float4*)&ks[j][0];
            float4 k1 = *(float4*)&ks[j][4];
            float dot = q0.x*k0.x + q0.y*k0.y + q0.z*k0.z + q0.w*k0.w
                      + q1.x*k1.x + q1.y*k1.y + q1.z*k1.z + q1.w*k1.w;
            mx = fmaxf(mx, dot);
            sm += dot;
        }
        sp[l] = mx - sm / (float)NP;
    }
    __syncthreads();

    if (w == 0) {
        float vals[16];
        #pragma unroll
        for (int jj = 0; jj < 16; jj++) {
            int l = lane + 32 * jj;
            vals[jj] = (l < NP) ? sp[l] : -INFINITY;
        }
        for (int it = 0; it < UP; it++) {
            float bv = -INFINITY; int bi = NP;
            #pragma unroll
            for (int jj = 0; jj < 16; jj++) {
                int l = lane + 32 * jj;
                float v = vals[jj];
                if (v > bv) { bv = v; bi = l; }
            }
            #pragma unroll
            for (int off = 16; off; off >>= 1) {
                float ov = __shfl_xor_sync(0xffffffffu, bv, off);
                int   oi = __shfl_xor_sync(0xffffffffu, bi, off);
                if (ov > bv || (ov == bv && oi < bi)) { bv = ov; bi = oi; }
            }
            if (lane == 0) g_top[blockIdx.x * UP + it] = bi;
            int tgt = bi >> 5;
            if ((bi & 31) == lane) {
                #pragma unroll
                for (int jj = 0; jj < 16; jj++)
                    if (jj == tgt) vals[jj] = -INFINITY;
            }
        }
    }
}

// ---------------- dense attention for selected queries (online softmax) ----
__global__ __launch_bounds__(256)
void attn_dense_kernel() {
    __shared__ float ks[NP][8];
    __shared__ float vs[NP][8];
    __shared__ int   top[UP];
    int bm = blockIdx.x / H_, h = blockIdx.x % H_;
    int t = threadIdx.x, lane = t & 31, w = t >> 5;
    long rbase = (long)bm * NP;

    const float4* gk4 = (const float4*)g_k;
    const float4* gv4 = (const float4*)g_v;
    const float4* gq4 = (const float4*)g_q;
    for (int i = t; i < NP * 2; i += 256) {
        int l = i >> 1, half = i & 1;
        long src = (rbase + l) * 16 + h * 2 + half;
        ((float4*)ks)[i] = gk4[src];
        ((float4*)vs)[i] = gv4[src];
    }
    if (t < UP) top[t] = g_top[blockIdx.x * UP + t];
    __syncthreads();

    float4* gc4 = (float4*)g_ctx;
    const float scale = 0.35355339059327373f;
    for (int i = w; i < UP; i += 8) {
        int l = top[i];
        long qb = (rbase + l) * 16 + h * 2;
        float4 q0 = gq4[qb], q1 = gq4[qb + 1];
        float m = -INFINITY, sum = 0.f;
        float4 a0 = make_float4(0.f, 0.f, 0.f, 0.f);
        float4 a1 = make_float4(0.f, 0.f, 0.f, 0.f);
        #pragma unroll 4
        for (int jj = 0; jj < 16; jj++) {
            int j = lane + 32 * jj;
            float s;
            if (j < NP) {
                float4 k0 = *(float4*)&ks[j][0];
                float4 k1 = *(float4*)&ks[j][4];
                s = (q0.x*k0.x + q0.y*k0.y + q0.z*k0.z + q0.w*k0.w
                   + q1.x*k1.x + q1.y*k1.y + q1.z*k1.z + q1.w*k1.w) * scale;
            } else s = -INFINITY;
            float mn = fmaxf(m, s);
            float corr = __expf(m - mn);     // 0 on first iter, 1 when no new max
            float p    = __expf(s - mn);     // 0 for invalid lanes
            sum = sum * corr + p;
            if (j < NP) {
                float4 v0 = *(float4*)&vs[j][0];
                float4 v1 = *(float4*)&vs[j][4];
                a0.x = a0.x * corr + p * v0.x; a0.y = a0.y * corr + p * v0.y;
                a0.z = a0.z * corr + p * v0.z; a0.w = a0.w * corr + p * v0.w;
                a1.x = a1.x * corr + p * v1.x; a1.y = a1.y * corr + p * v1.y;
                a1.z = a1.z * corr + p * v1.z; a1.w = a1.w * corr + p * v1.w;
            } else {
                a0.x *= corr; a0.y *= corr; a0.z *= corr; a0.w *= corr;
                a1.x *= corr; a1.y *= corr; a1.z *= corr; a1.w *= corr;
            }
            m = mn;
        }
        // reduce: global max, rescale once, then plain sums
        float M = m;
        #pragma unroll
        for (int off = 16; off; off >>= 1)
            M = fmaxf(M, __shfl_xor_sync(0xffffffffu, M, off));
        float c = __expf(m - M);
        sum *= c;
        a0.x *= c; a0.y *= c; a0.z *= c; a0.w *= c;
        a1.x *= c; a1.y *= c; a1.z *= c; a1.w *= c;
        #pragma unroll
        for (int off = 16; off; off >>= 1) {
            sum  += __shfl_xor_sync(0xffffffffu, sum, off);
            a0.x += __shfl_xor_sync(0xffffffffu, a0.x, off);
            a0.y += __shfl_xor_sync(0xffffffffu, a0.y, off);
            a0.z += __shfl_xor_sync(0xffffffffu, a0.z, off);
            a0.w += __shfl_xor_sync(0xffffffffu, a0.w, off);
            a1.x += __shfl_xor_sync(0xffffffffu, a1.x, off);
            a1.y += __shfl_xor_sync(0xffffffffu, a1.y, off);
            a1.z += __shfl_xor_sync(0xffffffffu, a1.z, off);
            a1.w += __shfl_xor_sync(0xffffffffu, a1.w, off);
        }
        if (lane == 0) {
            float inv = 1.f / sum;
            gc4[qb]     = make_float4(a0.x*inv, a0.y*inv, a0.z*inv, a0.w*inv);
            gc4[qb + 1] = make_float4(a1.x*inv, a1.y*inv, a1.z*inv, a1.w*inv);
        }
    }
}

// ---------------- Wo GEMM + residual + LN1 ----------------
__global__ __launch_bounds__(256)
void wo_ln1_kernel(const float* __restrict__ Wo, const float* __restrict__ bo,
                   const float* __restrict__ g1, const float* __restrict__ b1) {
    extern __shared__ char smem_raw[];
    SmemG128* S = (SmemG128*)smem_raw;
    int t = threadIdx.x;
    int r0 = blockIdx.x * 128;
    int rows = NROW - r0; if (rows > 128) rows = 128;

    for (int i = t; i < 128 * 16; i += 256) {
        int row = i / 16, f4 = i % 16;
        float4 v = make_float4(0.f, 0.f, 0.f, 0.f);
        if (row < rows) v = *(const float4*)&g_ctx[(r0 + row) * DM + f4 * 4];
        *(float4*)&S->As[row][f4 * 4] = v;
    }
    {
        int c = t >> 2, ks0 = (t & 3) * 16;
        #pragma unroll
        for (int q = 0; q < 4; q++) {
            float4 wv = *(const float4*)&Wo[c * 64 + ks0 + q * 4];
            S->Bs[ks0 + q * 4 + 0][c] = wv.x;
            S->Bs[ks0 + q * 4 + 1][c] = wv.y;
            S->Bs[ks0 + q * 4 + 2][c] = wv.z;
            S->Bs[ks0 + q * 4 + 3][c] = wv.w;
        }
    }
    __syncthreads();
    int rg = t >> 4, cg = t & 15;
    float4 acc[8];
    #pragma unroll
    for (int r = 0; r < 8; r++) acc[r] = make_float4(0.f, 0.f, 0.f, 0.f);
    #pragma unroll
    for (int k = 0; k < 64; k += 4) {
        float4 b0 = *(float4*)&S->Bs[k + 0][cg * 4];
        float4 b1v = *(float4*)&S->Bs[k + 1][cg * 4];
        float4 b2 = *(float4*)&S->Bs[k + 2][cg * 4];
        float4 b3 = *(float4*)&S->Bs[k + 3][cg * 4];
        #pragma unroll
        for (int r = 0; r < 8; r++) {
            float4 a = *(float4*)&S->As[rg * 8 + r][k];
            fma4(acc[r], a.x, b0); fma4(acc[r], a.y, b1v);
            fma4(acc[r], a.z, b2); fma4(acc[r], a.w, b3);
        }
    }
    __syncthreads();
    float4 bb = *(const float4*)&bo[cg * 4];
    #pragma unroll
    for (int r = 0; r < 8; r++) {
        int row = rg * 8 + r;
        if (row < rows) {
            float4 z = *(const float4*)&g_z[(r0 + row) * DM + cg * 4];
            S->As[row][cg * 4 + 0] = acc[r].x + bb.x + z.x;
            S->As[row][cg * 4 + 1] = acc[r].y + bb.y + z.y;
            S->As[row][cg * 4 + 2] = acc[r].z + bb.z + z.z;
            S->As[row][cg * 4 + 3] = acc[r].w + bb.w + z.w;
        }
    }
    __syncthreads();
    int lane = t & 31, w2 = t >> 5;
    for (int rr = 0; rr < 16; rr++) {
        int row = w2 * 16 + rr;
        if (row >= rows) break;
        float v0 = S->As[row][lane], v1 = S->As[row][lane + 32];
        float s = v0 + v1;
        #pragma unroll
        for (int o = 16; o; o >>= 1) s += __shfl_xor_sync(0xffffffffu, s, o);
        float mu = s / 64.f;
        float d0 = v0 - mu, d1 = v1 - mu;
        float vv = d0 * d0 + d1 * d1;
        #pragma unroll
        for (int o = 16; o; o >>= 1) vv += __shfl_xor_sync(0xffffffffu, vv, o);
        float inv = rsqrtf(vv / 64.f + 1e-5f);
        g_x1[(r0 + row) * DM + lane]      = d0 * inv * g1[lane]      + b1[lane];
        g_x1[(r0 + row) * DM + lane + 32] = d1 * inv * g1[lane + 32] + b1[lane + 32];
    }
}

// ---------------- fused FFN + residual + LN2 ----------------
struct SmemFFN {
    float xs[64][68];
    float wb[64][68];
    float ys[64][260];
};

__global__ __launch_bounds__(256)
void ffn_ln2_kernel(const float* __restrict__ W1, const float* __restrict__ b1f,
                    const float* __restrict__ W2, const float* __restrict__ b2f,
                    const float* __restrict__ g2, const float* __restrict__ bb2) {
    extern __shared__ char smem_raw[];
    SmemFFN* S = (SmemFFN*)smem_raw;
    int t = threadIdx.x;
    int r0 = blockIdx.x * 64;
    int rg = t >> 4, cg = t & 15;
    int cw = t >> 2, ks0 = (t & 3) * 16;

    for (int i = t; i < 64 * 16; i += 256) {
        int row = i / 16, f4 = i % 16;
        *(float4*)&S->xs[row][f4 * 4] = *(const float4*)&g_x1[(r0 + row) * DM + f4 * 4];
    }

    for (int cc = 0; cc < 4; cc++) {
        __syncthreads();
        #pragma unroll
        for (int q = 0; q < 4; q++) {
            float4 wv = *(const float4*)&W1[(cc * 64 + cw) * 64 + ks0 + q * 4];
            S->wb[ks0 + q * 4 + 0][cw] = wv.x;
            S->wb[ks0 + q * 4 + 1][cw] = wv.y;
            S->wb[ks0 + q * 4 + 2][cw] = wv.z;
            S->wb[ks0 + q * 4 + 3][cw] = wv.w;
        }
        __syncthreads();
        float4 acc[4];
        #pragma unroll
        for (int r = 0; r < 4; r++) acc[r] = make_float4(0.f, 0.f, 0.f, 0.f);
        #pragma unroll
        for (int k = 0; k < 64; k += 4) {
            float4 b0 = *(float4*)&S->wb[k + 0][cg * 4];
            float4 b1 = *(float4*)&S->wb[k + 1][cg * 4];
            float4 b2 = *(float4*)&S->wb[k + 2][cg * 4];
            float4 b3 = *(float4*)&S->wb[k + 3][cg * 4];
            #pragma unroll
            for (int r = 0; r < 4; r++) {
                float4 a = *(float4*)&S->xs[rg * 4 + r][k];
                fma4(acc[r], a.x, b0); fma4(acc[r], a.y, b1);
                fma4(acc[r], a.z, b2); fma4(acc[r], a.w, b3);
            }
        }
        float4 bb = *(const float4*)&b1f[cc * 64 + cg * 4];
        #pragma unroll
        for (int r = 0; r < 4; r++) {
            float x0 = acc[r].x + bb.x, x1 = acc[r].y + bb.y;
            float x2 = acc[r].z + bb.z, x3 = acc[r].w + bb.w;
            float4 y;
            y.x = x0 * 0.5f * (1.f + erff(x0 * 0.7071067811865476f));
            y.y = x1 * 0.5f * (1.f + erff(x1 * 0.7071067811865476f));
            y.z = x2 * 0.5f * (1.f + erff(x2 * 0.7071067811865476f));
            y.w = x3 * 0.5f * (1.f + erff(x3 * 0.7071067811865476f));
            *(float4*)&S->ys[rg * 4 + r][cc * 64 + cg * 4] = y;
        }
    }

    float4 acc2[4];
    #pragma unroll
    for (int r = 0; r < 4; r++) acc2[r] = make_float4(0.f, 0.f, 0.f, 0.f);
    for (int kc = 0; kc < 4; kc++) {
        __syncthreads();
        #pragma unroll
        for (int q = 0; q < 4; q++) {
            float4 wv = *(const float4*)&W2[cw * 256 + kc * 64 + ks0 + q * 4];
            S->wb[ks0 + q * 4 + 0][cw] = wv.x;
            S->wb[ks0 + q * 4 + 1][cw] = wv.y;
            S->wb[ks0 + q * 4 + 2][cw] = wv.z;
            S->wb[ks0 + q * 4 + 3][cw] = wv.w;
        }
        __syncthreads();
        #pragma unroll
        for (int k = 0; k < 64; k += 4) {
            float4 b0 = *(float4*)&S->wb[k + 0][cg * 4];
            float4 b1 = *(float4*)&S->wb[k + 1][cg * 4];
            float4 b2 = *(float4*)&S->wb[k + 2][cg * 4];
            float4 b3 = *(float4*)&S->wb[k + 3][cg * 4];
            #pragma unroll
            for (int r = 0; r < 4; r++) {
                float4 a = *(float4*)&S->ys[rg * 4 + r][kc * 64 + k];
                fma4(acc2[r], a.x, b0); fma4(acc2[r], a.y, b1);
                fma4(acc2[r], a.z, b2); fma4(acc2[r], a.w, b3);
            }
        }
    }
    __syncthreads();
    {
        float4 bb = *(const float4*)&b2f[cg * 4];
        #pragma unroll
        for (int r = 0; r < 4; r++) {
            int row = rg * 4 + r;
            S->xs[row][cg * 4 + 0] += acc2[r].x + bb.x;
            S->xs[row][cg * 4 + 1] += acc2[r].y + bb.y;
            S->xs[row][cg * 4 + 2] += acc2[r].z + bb.z;
            S->xs[row][cg * 4 + 3] += acc2[r].w + bb.w;
        }
    }
    __syncthreads();
    int lane = t & 31, w2 = t >> 5;
    #pragma unroll
    for (int rr = 0; rr < 8; rr++) {
        int row = w2 * 8 + rr;
        float v0 = S->xs[row][lane], v1 = S->xs[row][lane + 32];
        float s = v0 + v1;
        #pragma unroll
        for (int o = 16; o; o >>= 1) s += __shfl_xor_sync(0xffffffffu, s, o);
        float mu = s / 64.f;
        float d0 = v0 - mu, d1 = v1 - mu;
        float vv = d0 * d0 + d1 * d1;
        #pragma unroll
        for (int o = 16; o; o >>= 1) vv += __shfl_xor_sync(0xffffffffu, vv, o);
        float inv = rsqrtf(vv / 64.f + 1e-5f);
        g_z[(r0 + row) * DM + lane]      = d0 * inv * g2[lane]      + bb2[lane];
        g_z[(r0 + row) * DM + lane + 32] = d1 * inv * g2[lane + 32] + bb2[lane + 32];
    }
}

// ---------------- final LN ----------------
__global__ void final_ln_kernel(const float* __restrict__ gf, const float* __restrict__ bf) {
    int t = threadIdx.x, lane = t & 31, w = t >> 5;
    int r = blockIdx.x * 8 + w;
    float v0 = g_z[r * DM + lane], v1 = g_z[r * DM + lane + 32];
    float s = v0 + v1;
    #pragma unroll
    for (int o = 16; o; o >>= 1) s += __shfl_xor_sync(0xffffffffu, s, o);
    float mu = s / 64.f;
    float d0 = v0 - mu, d1 = v1 - mu;
    float vv = d0 * d0 + d1 * d1;
    #pragma unroll
    for (int o = 16; o; o >>= 1) vv += __shfl_xor_sync(0xffffffffu, vv, o);
    float inv = rsqrtf(vv / 64.f + 1e-5f);
    g_z[r * DM + lane]      = d0 * inv * gf[lane]      + bf[lane];
    g_z[r * DM + lane + 32] = d1 * inv * gf[lane + 32] + bf[lane + 32];
}

// ---------------- output projection ----------------
__global__ void proj_partial_kernel(const float* __restrict__ outW) {
    int seg = blockIdx.x;
    int bg  = blockIdx.y;
    __shared__ float zc[8][SEG];
    int t = threadIdx.x, lane = t & 31, w = t >> 5;
    int k0 = seg * SEG;
    for (int i = t; i < 8 * SEG; i += 256) {
        int bmo = i / SEG, kk = i % SEG;
        zc[bmo][kk] = g_z[(bg * 8 + bmo) * KTOT + k0 + kk];
    }
    __syncthreads();
    for (int p = w; p < PRED; p += 8) {
        float acc[8] = {0.f, 0.f, 0.f, 0.f, 0.f, 0.f, 0.f, 0.f};
        for (int kk = lane; kk < SEG; kk += 32) {
            float ww = outW[p * KTOT + k0 + kk];
            #pragma unroll
            for (int bmo = 0; bmo < 8; bmo++) acc[bmo] += ww * zc[bmo][kk];
        }
        #pragma unroll
        for (int bmo = 0; bmo < 8; bmo++) {
            #pragma unroll
            for (int o = 16; o; o >>= 1)
                acc[bmo] += __shfl_xor_sync(0xffffffffu, acc[bmo], o);
        }
        if (lane == 0) {
            #pragma unroll
            for (int bmo = 0; bmo < 8; bmo++)
                g_pp[(p * BM + bg * 8 + bmo) * NSEG + seg] = acc[bmo];
        }
    }
}

__global__ void proj_reduce_kernel(const float* __restrict__ outb, float* __restrict__ out) {
    int i = blockIdx.x * 256 + threadIdx.x;
    if (i >= PRED * BM) return;
    int p = i / BM, bm = i % BM;
    float s = outb[p];
    #pragma unroll
    for (int seg = 0; seg < NSEG; seg++) s += g_pp[(p * BM + bm) * NSEG + seg];
    int b = bm / M_, m = bm % M_;
    out[(b * PRED + p) * M_ + m] = s;
}

// ---------------- launch ----------------
extern "C" void kernel_launch(void* const* d_in, const int* in_sizes, int n_in,
                              void* d_out, int out_size) {
    const float* x_enc = (const float*)d_in[0];
    const float* in_W  = (const float*)d_in[4];
    const float* in_b  = (const float*)d_in[5];
    const float* Wq    = (const float*)d_in[6];
    const float* bq    = (const float*)d_in[7];
    const float* Wk    = (const float*)d_in[8];
    const float* bk    = (const float*)d_in[9];
    const float* Wv    = (const float*)d_in[10];
    const float* bv    = (const float*)d_in[11];
    const float* Wo    = (const float*)d_in[12];
    const float* bo    = (const float*)d_in[13];
    const float* c1_W  = (const float*)d_in[14];
    const float* c1_b  = (const float*)d_in[15];
    const float* c2_W  = (const float*)d_in[16];
    const float* c2_b  = (const float*)d_in[17];
    const float* ln1_g = (const float*)d_in[18];
    const float* ln1_b = (const float*)d_in[19];
    const float* ln2_g = (const float*)d_in[20];
    const float* ln2_b = (const float*)d_in[21];
    const float* lnf_g = (const float*)d_in[22];
    const float* lnf_b = (const float*)d_in[23];
    const float* out_W = (const float*)d_in[24];
    const float* out_b = (const float*)d_in[25];
    float* out = (float*)d_out;

    const int smemG = sizeof(SmemG128);
    const int smemF = sizeof(SmemFFN);
    cudaFuncSetAttribute(qkv_kernel,    cudaFuncAttributeMaxDynamicSharedMemorySize, smemG);
    cudaFuncSetAttribute(wo_ln1_kernel, cudaFuncAttributeMaxDynamicSharedMemorySize, smemG);
    cudaFuncSetAttribute(ffn_ln2_kernel,cudaFuncAttributeMaxDynamicSharedMemorySize, smemF);

    patch_embed_kernel<<<NROW / 16, 256>>>(x_enc, in_W, in_b);

    for (int e = 0; e < 2; e++) {
        rand_idx_kernel<<<(NP * UP + 255) / 256, 256>>>(e);
        qkv_kernel<<<dim3(256, 3), 256, smemG>>>(Wq + e * DM * DM, bq + e * DM,
                                                 Wk + e * DM * DM, bk + e * DM,
                                                 Wv + e * DM * DM, bv + e * DM);
        topk_kernel<<<BM * H_, 256>>>();
        vmean_kernel<<<BM, 256>>>();
        bcast_kernel<<<NROW * 16 / 256, 256>>>();
        attn_dense_kernel<<<BM * H_, 256>>>();
        wo_ln1_kernel<<<256, 256, smemG>>>(Wo + e * DM * DM, bo + e * DM,
                                           ln1_g + e * DM, ln1_b + e * DM);
        ffn_ln2_kernel<<<NROW / 64, 256, smemF>>>(c1_W + e * DFF * DM, c1_b + e * DFF,
                                                  c2_W + e * DM * DFF, c2_b + e * DM,
                                                  ln2_g + e * DM, ln2_b + e * DM);
    }

    final_ln_kernel<<<NROW / 8, 256>>>(lnf_g, lnf_b);
    proj_partial_kernel<<<dim3(NSEG, 8), 256>>>(out_W);
    proj_reduce_kernel<<<(PRED * BM + 255) / 256, 256>>>(out_b, out);
}

// round 5
// speedup vs baseline: 8.3891x; 1.1248x over previous
#include <cuda_runtime.h>
#include <cstdint>
#include <math.h>

#define B_      8
#define M_      8
#define BM      64
#define SL      4096
#define P_      16
#define STRIDE_ 8
#define NP      511
#define DM      64
#define H_      8
#define DH      8
#define DFF     256
#define PRED    96
#define UP      35
#define NROW    (BM*NP)      // 32704
#define KTOT    (NP*DM)      // 32704
#define NSEG    32
#define SEG     1022

// ---------------- scratch ----------------
__device__ float g_z  [NROW*DM];
__device__ float g_q  [NROW*DM];
__device__ float g_k  [NROW*DM];
__device__ float g_v  [NROW*DM];
__device__ float g_ctx[NROW*DM];
__device__ float g_x1 [NROW*DM];
__device__ int   g_idxT[UP*NP];          // transposed: [u][l]
__device__ int   g_top[BM*H_*UP];
__device__ float g_vmean[BM*DM];
__device__ float g_pp [PRED*BM*NSEG];

__device__ __forceinline__ void fma4(float4& o, float s, const float4& b) {
    o.x += s * b.x; o.y += s * b.y; o.z += s * b.z; o.w += s * b.w;
}

// ---------------- threefry2x32 (bitwise JAX-compatible) ----------------
__device__ __forceinline__ uint32_t rotl32(uint32_t v, int r) {
    return (v << r) | (v >> (32 - r));
}

__device__ __forceinline__ void tf2x32(uint32_t k0, uint32_t k1,
                                       uint32_t& x0, uint32_t& x1) {
    uint32_t ks0 = k0, ks1 = k1, ks2 = k0 ^ k1 ^ 0x1BD11BDAu;
    const int ra[4] = {13, 15, 26, 6};
    const int rb[4] = {17, 29, 16, 24};
    x0 += ks0; x1 += ks1;
    #pragma unroll
    for (int i = 0; i < 4; i++) { x0 += x1; x1 = rotl32(x1, ra[i]); x1 ^= x0; }
    x0 += ks1; x1 += ks2 + 1u;
    #pragma unroll
    for (int i = 0; i < 4; i++) { x0 += x1; x1 = rotl32(x1, rb[i]); x1 ^= x0; }
    x0 += ks2; x1 += ks0 + 2u;
    #pragma unroll
    for (int i = 0; i < 4; i++) { x0 += x1; x1 = rotl32(x1, ra[i]); x1 ^= x0; }
    x0 += ks0; x1 += ks1 + 3u;
    #pragma unroll
    for (int i = 0; i < 4; i++) { x0 += x1; x1 = rotl32(x1, rb[i]); x1 ^= x0; }
    x0 += ks1; x1 += ks2 + 4u;
    #pragma unroll
    for (int i = 0; i < 4; i++) { x0 += x1; x1 = rotl32(x1, ra[i]); x1 ^= x0; }
    x0 += ks2; x1 += ks0 + 5u;
}

__device__ __forceinline__ uint32_t rbits17885(uint32_t k0, uint32_t k1, int j) {
    const int HALF = 8943;
    uint32_t x0, x1;
    if (j < HALF) {
        x0 = (uint32_t)j;
        x1 = (j < HALF - 1) ? (uint32_t)(j + HALF) : 0u;
        tf2x32(k0, k1, x0, x1);
        return x0;
    } else {
        x0 = (uint32_t)(j - HALF);
        x1 = (uint32_t)j;
        tf2x32(k0, k1, x0, x1);
        return x1;
    }
}

__global__ void rand_idx_kernel(int e) {
    uint32_t f0 = 0u, f1 = (uint32_t)e;
    tf2x32(0u, 1u, f0, f1);
    uint32_t a0 = 0u, a1 = 2u; tf2x32(f0, f1, a0, a1);
    uint32_t b0 = 1u, b1 = 3u; tf2x32(f0, f1, b0, b1);
    int j = blockIdx.x * blockDim.x + threadIdx.x;   // bit-stream position (row-major l,u)
    if (j >= NP * UP) return;
    uint32_t hi = rbits17885(a0, b0, j);
    uint32_t lo = rbits17885(a1, b1, j);
    uint32_t off = ((hi % 511u) * 32u + (lo % 511u)) % 511u;
    int l = j / UP, u = j % UP;
    g_idxT[u * NP + l] = (int)off;                   // store transposed
}

// ---------------- patch embedding ----------------
__global__ void patch_embed_kernel(const float* __restrict__ xe,
                                   const float* __restrict__ inW,
                                   const float* __restrict__ inb) {
    __shared__ float ps[16][17];
    __shared__ float ws[64][17];
    __shared__ float bs[64];
    int t = threadIdx.x;
    int r0 = blockIdx.x * 16;
    {
        int rr = t / 16, p = t % 16;
        int r = r0 + rr;
        int bm = r / NP, n = r % NP;
        int b = bm / M_, m = bm % M_;
        ps[rr][p] = xe[(b * SL + n * STRIDE_ + p) * M_ + m];
    }
    for (int i = t; i < 64 * P_; i += 256) ws[i / P_][i % P_] = inW[i];
    if (t < 64) bs[t] = inb[t];
    __syncthreads();
    int c = t % 64, q4 = t / 64;
    #pragma unroll
    for (int rr = q4 * 4; rr < q4 * 4 + 4; rr++) {
        float acc = bs[c];
        #pragma unroll
        for (int p = 0; p < P_; p++) acc += ws[c][p] * ps[rr][p];
        g_z[(r0 + rr) * DM + c] = acc;
    }
}

// ---------------- QKV GEMM ----------------
struct SmemG128 {
    float As[128][68];
    float Bs[64][68];
};

__global__ __launch_bounds__(256)
void qkv_kernel(const float* __restrict__ Wq, const float* __restrict__ bq,
                const float* __restrict__ Wk, const float* __restrict__ bk,
                const float* __restrict__ Wv, const float* __restrict__ bv) {
    extern __shared__ char smem_raw[];
    SmemG128* S = (SmemG128*)smem_raw;
    int t = threadIdx.x;
    int r0 = blockIdx.x * 128;
    int rows = NROW - r0; if (rows > 128) rows = 128;
    const float* W; const float* bias; float* out;
    if (blockIdx.y == 0)      { W = Wq; bias = bq; out = g_q; }
    else if (blockIdx.y == 1) { W = Wk; bias = bk; out = g_k; }
    else                      { W = Wv; bias = bv; out = g_v; }

    for (int i = t; i < 128 * 16; i += 256) {
        int row = i / 16, f4 = i % 16;
        float4 v = make_float4(0.f, 0.f, 0.f, 0.f);
        if (row < rows) v = *(const float4*)&g_z[(r0 + row) * DM + f4 * 4];
        *(float4*)&S->As[row][f4 * 4] = v;
    }
    {
        int c = t >> 2, ks0 = (t & 3) * 16;
        #pragma unroll
        for (int q = 0; q < 4; q++) {
            float4 wv = *(const float4*)&W[c * 64 + ks0 + q * 4];
            S->Bs[ks0 + q * 4 + 0][c] = wv.x;
            S->Bs[ks0 + q * 4 + 1][c] = wv.y;
            S->Bs[ks0 + q * 4 + 2][c] = wv.z;
            S->Bs[ks0 + q * 4 + 3][c] = wv.w;
        }
    }
    __syncthreads();
    int rg = t >> 4, cg = t & 15;
    float4 acc[8];
    #pragma unroll
    for (int r = 0; r < 8; r++) acc[r] = make_float4(0.f, 0.f, 0.f, 0.f);
    #pragma unroll
    for (int k = 0; k < 64; k += 4) {
        float4 b0 = *(float4*)&S->Bs[k + 0][cg * 4];
        float4 b1 = *(float4*)&S->Bs[k + 1][cg * 4];
        float4 b2 = *(float4*)&S->Bs[k + 2][cg * 4];
        float4 b3 = *(float4*)&S->Bs[k + 3][cg * 4];
        #pragma unroll
        for (int r = 0; r < 8; r++) {
            float4 a = *(float4*)&S->As[rg * 8 + r][k];
            fma4(acc[r], a.x, b0); fma4(acc[r], a.y, b1);
            fma4(acc[r], a.z, b2); fma4(acc[r], a.w, b3);
        }
    }
    float4 bb = *(const float4*)&bias[cg * 4];
    #pragma unroll
    for (int r = 0; r < 8; r++) {
        int row = rg * 8 + r;
        if (row < rows) {
            float4 o = make_float4(acc[r].x + bb.x, acc[r].y + bb.y,
                                   acc[r].z + bb.z, acc[r].w + bb.w);
            *(float4*)&out[(r0 + row) * DM + cg * 4] = o;
        }
    }
}

// ---------------- V mean per bm ----------------
__global__ __launch_bounds__(256)
void vmean_kernel() {
    __shared__ float part[4][64];
    int bm = blockIdx.x;
    int t = threadIdx.x;
    int col = t & 63, slice = t >> 6;
    float s = 0.f;
    for (int l = slice; l < NP; l += 4) s += g_v[(bm * NP + l) * DM + col];
    part[slice][col] = s;
    __syncthreads();
    if (t < 64) {
        float v = (part[0][t] + part[1][t] + part[2][t] + part[3][t]) / (float)NP;
        g_vmean[bm * DM + t] = v;
    }
}

// ---------------- broadcast vmean into g_ctx ----------------
__global__ __launch_bounds__(256)
void bcast_kernel() {
    int i = blockIdx.x * 256 + threadIdx.x;
    int row = i >> 4, f4 = i & 15;
    int bm = row / NP;
    ((float4*)g_ctx)[i] = ((const float4*)g_vmean)[bm * 16 + f4];
}

// ---------------- sparsity + top-k ----------------
__global__ __launch_bounds__(256)
void topk_kernel() {
    __shared__ float4 klo[NP];
    __shared__ float4 khi[NP];
    __shared__ float sp[512];
    int bm = blockIdx.x / H_, h = blockIdx.x % H_;
    int t = threadIdx.x, lane = t & 31, w = t >> 5;
    long rbase = (long)bm * NP;

    const float4* gk4 = (const float4*)g_k;
    const float4* gq4 = (const float4*)g_q;
    for (int i = t; i < NP * 2; i += 256) {
        int l = i >> 1, half = i & 1;
        float4 v = gk4[(rbase + l) * 16 + h * 2 + half];
        if (half == 0) klo[l] = v; else khi[l] = v;
    }
    __syncthreads();

    for (int l = t; l < NP; l += 256) {
        long qb = (rbase + l) * 16 + h * 2;
        float4 q0 = gq4[qb], q1 = gq4[qb + 1];
        float mx = -INFINITY, sm = 0.f;
        #pragma unroll 7
        for (int u = 0; u < UP; u++) {
            int j = g_idxT[u * NP + l];          // coalesced across lanes
            float4 k0 = klo[j];
            float4 k1 = khi[j];
            float dot = q0.x*k0.x + q0.y*k0.y + q0.z*k0.z + q0.w*k0.w
                      + q1.x*k1.x + q1.y*k1.y + q1.z*k1.z + q1.w*k1.w;
            mx = fmaxf(mx, dot);
            sm += dot;
        }
        sp[l] = mx - sm / (float)NP;
    }
    __syncthreads();

    if (w == 0) {
        float vals[16];
        #pragma unroll
        for (int jj = 0; jj < 16; jj++) {
            int l = lane + 32 * jj;
            vals[jj] = (l < NP) ? sp[l] : -INFINITY;
        }
        for (int it = 0; it < UP; it++) {
            float bv = -INFINITY; int bi = NP;
            #pragma unroll
            for (int jj = 0; jj < 16; jj++) {
                int l = lane + 32 * jj;
                float v = vals[jj];
                if (v > bv) { bv = v; bi = l; }
            }
            #pragma unroll
            for (int off = 16; off; off >>= 1) {
                float ov = __shfl_xor_sync(0xffffffffu, bv, off);
                int   oi = __shfl_xor_sync(0xffffffffu, bi, off);
                if (ov > bv || (ov == bv && oi < bi)) { bv = ov; bi = oi; }
            }
            if (lane == 0) g_top[blockIdx.x * UP + it] = bi;
            int tgt = bi >> 5;
            if ((bi & 31) == lane) {
                #pragma unroll
                for (int jj = 0; jj < 16; jj++)
                    if (jj == tgt) vals[jj] = -INFINITY;
            }
        }
    }
}

// ---------------- dense attention for selected queries (online softmax) ----
__global__ __launch_bounds__(256)
void attn_dense_kernel() {
    __shared__ float4 klo[NP];
    __shared__ float4 khi[NP];
    __shared__ float4 vlo[NP];
    __shared__ float4 vhi[NP];
    __shared__ int   top[UP];
    int bm = blockIdx.x / H_, h = blockIdx.x % H_;
    int t = threadIdx.x, lane = t & 31, w = t >> 5;
    long rbase = (long)bm * NP;

    const float4* gk4 = (const float4*)g_k;
    const float4* gv4 = (const float4*)g_v;
    const float4* gq4 = (const float4*)g_q;
    for (int i = t; i < NP * 2; i += 256) {
        int l = i >> 1, half = i & 1;
        long src = (rbase + l) * 16 + h * 2 + half;
        float4 kv = gk4[src];
        float4 vv = gv4[src];
        if (half == 0) { klo[l] = kv; vlo[l] = vv; }
        else           { khi[l] = kv; vhi[l] = vv; }
    }
    if (t < UP) top[t] = g_top[blockIdx.x * UP + t];
    __syncthreads();

    float4* gc4 = (float4*)g_ctx;
    const float scale = 0.35355339059327373f;
    for (int i = w; i < UP; i += 8) {
        int l = top[i];
        long qb = (rbase + l) * 16 + h * 2;
        float4 q0 = gq4[qb], q1 = gq4[qb + 1];
        float m = -INFINITY, sum = 0.f;
        float4 a0 = make_float4(0.f, 0.f, 0.f, 0.f);
        float4 a1 = make_float4(0.f, 0.f, 0.f, 0.f);
        #pragma unroll 4
        for (int jj = 0; jj < 16; jj++) {
            int j = lane + 32 * jj;
            float s;
            if (j < NP) {
                float4 k0 = klo[j];
                float4 k1 = khi[j];
                s = (q0.x*k0.x + q0.y*k0.y + q0.z*k0.z + q0.w*k0.w
                   + q1.x*k1.x + q1.y*k1.y + q1.z*k1.z + q1.w*k1.w) * scale;
            } else s = -INFINITY;
            float mn = fmaxf(m, s);
            float corr = __expf(m - mn);
            float p    = __expf(s - mn);
            sum = sum * corr + p;
            if (j < NP) {
                float4 v0 = vlo[j];
                float4 v1 = vhi[j];
                a0.x = a0.x * corr + p * v0.x; a0.y = a0.y * corr + p * v0.y;
                a0.z = a0.z * corr + p * v0.z; a0.w = a0.w * corr + p * v0.w;
                a1.x = a1.x * corr + p * v1.x; a1.y = a1.y * corr + p * v1.y;
                a1.z = a1.z * corr + p * v1.z; a1.w = a1.w * corr + p * v1.w;
            } else {
                a0.x *= corr; a0.y *= corr; a0.z *= corr; a0.w *= corr;
                a1.x *= corr; a1.y *= corr; a1.z *= corr; a1.w *= corr;
            }
            m = mn;
        }
        float M = m;
        #pragma unroll
        for (int off = 16; off; off >>= 1)
            M = fmaxf(M, __shfl_xor_sync(0xffffffffu, M, off));
        float c = __expf(m - M);
        sum *= c;
        a0.x *= c; a0.y *= c; a0.z *= c; a0.w *= c;
        a1.x *= c; a1.y *= c; a1.z *= c; a1.w *= c;
        #pragma unroll
        for (int off = 16; off; off >>= 1) {
            sum  += __shfl_xor_sync(0xffffffffu, sum, off);
            a0.x += __shfl_xor_sync(0xffffffffu, a0.x, off);
            a0.y += __shfl_xor_sync(0xffffffffu, a0.y, off);
            a0.z += __shfl_xor_sync(0xffffffffu, a0.z, off);
            a0.w += __shfl_xor_sync(0xffffffffu, a0.w, off);
            a1.x += __shfl_xor_sync(0xffffffffu, a1.x, off);
            a1.y += __shfl_xor_sync(0xffffffffu, a1.y, off);
            a1.z += __shfl_xor_sync(0xffffffffu, a1.z, off);
            a1.w += __shfl_xor_sync(0xffffffffu, a1.w, off);
        }
        if (lane == 0) {
            float inv = 1.f / sum;
            gc4[qb]     = make_float4(a0.x*inv, a0.y*inv, a0.z*inv, a0.w*inv);
            gc4[qb + 1] = make_float4(a1.x*inv, a1.y*inv, a1.z*inv, a1.w*inv);
        }
    }
}

// ---------------- Wo GEMM + residual + LN1 ----------------
__global__ __launch_bounds__(256)
void wo_ln1_kernel(const float* __restrict__ Wo, const float* __restrict__ bo,
                   const float* __restrict__ g1, const float* __restrict__ b1) {
    extern __shared__ char smem_raw[];
    SmemG128* S = (SmemG128*)smem_raw;
    int t = threadIdx.x;
    int r0 = blockIdx.x * 128;
    int rows = NROW - r0; if (rows > 128) rows = 128;

    for (int i = t; i < 128 * 16; i += 256) {
        int row = i / 16, f4 = i % 16;
        float4 v = make_float4(0.f, 0.f, 0.f, 0.f);
        if (row < rows) v = *(const float4*)&g_ctx[(r0 + row) * DM + f4 * 4];
        *(float4*)&S->As[row][f4 * 4] = v;
    }
    {
        int c = t >> 2, ks0 = (t & 3) * 16;
        #pragma unroll
        for (int q = 0; q < 4; q++) {
            float4 wv = *(const float4*)&Wo[c * 64 + ks0 + q * 4];
            S->Bs[ks0 + q * 4 + 0][c] = wv.x;
            S->Bs[ks0 + q * 4 + 1][c] = wv.y;
            S->Bs[ks0 + q * 4 + 2][c] = wv.z;
            S->Bs[ks0 + q * 4 + 3][c] = wv.w;
        }
    }
    __syncthreads();
    int rg = t >> 4, cg = t & 15;
    float4 acc[8];
    #pragma unroll
    for (int r = 0; r < 8; r++) acc[r] = make_float4(0.f, 0.f, 0.f, 0.f);
    #pragma unroll
    for (int k = 0; k < 64; k += 4) {
        float4 b0 = *(float4*)&S->Bs[k + 0][cg * 4];
        float4 b1v = *(float4*)&S->Bs[k + 1][cg * 4];
        float4 b2 = *(float4*)&S->Bs[k + 2][cg * 4];
        float4 b3 = *(float4*)&S->Bs[k + 3][cg * 4];
        #pragma unroll
        for (int r = 0; r < 8; r++) {
            float4 a = *(float4*)&S->As[rg * 8 + r][k];
            fma4(acc[r], a.x, b0); fma4(acc[r], a.y, b1v);
            fma4(acc[r], a.z, b2); fma4(acc[r], a.w, b3);
        }
    }
    __syncthreads();
    float4 bb = *(const float4*)&bo[cg * 4];
    #pragma unroll
    for (int r = 0; r < 8; r++) {
        int row = rg * 8 + r;
        if (row < rows) {
            float4 z = *(const float4*)&g_z[(r0 + row) * DM + cg * 4];
            S->As[row][cg * 4 + 0] = acc[r].x + bb.x + z.x;
            S->As[row][cg * 4 + 1] = acc[r].y + bb.y + z.y;
            S->As[row][cg * 4 + 2] = acc[r].z + bb.z + z.z;
            S->As[row][cg * 4 + 3] = acc[r].w + bb.w + z.w;
        }
    }
    __syncthreads();
    int lane = t & 31, w2 = t >> 5;
    for (int rr = 0; rr < 16; rr++) {
        int row = w2 * 16 + rr;
        if (row >= rows) break;
        float v0 = S->As[row][lane], v1 = S->As[row][lane + 32];
        float s = v0 + v1;
        #pragma unroll
        for (int o = 16; o; o >>= 1) s += __shfl_xor_sync(0xffffffffu, s, o);
        float mu = s / 64.f;
        float d0 = v0 - mu, d1 = v1 - mu;
        float vv = d0 * d0 + d1 * d1;
        #pragma unroll
        for (int o = 16; o; o >>= 1) vv += __shfl_xor_sync(0xffffffffu, vv, o);
        float inv = rsqrtf(vv / 64.f + 1e-5f);
        g_x1[(r0 + row) * DM + lane]      = d0 * inv * g1[lane]      + b1[lane];
        g_x1[(r0 + row) * DM + lane + 32] = d1 * inv * g1[lane + 32] + b1[lane + 32];
    }
}

// ---------------- fused FFN + residual + LN2 ----------------
struct SmemFFN {
    float xs[64][68];
    float wb[64][68];
    float ys[64][260];
};

__global__ __launch_bounds__(256)
void ffn_ln2_kernel(const float* __restrict__ W1, const float* __restrict__ b1f,
                    const float* __restrict__ W2, const float* __restrict__ b2f,
                    const float* __restrict__ g2, const float* __restrict__ bb2) {
    extern __shared__ char smem_raw[];
    SmemFFN* S = (SmemFFN*)smem_raw;
    int t = threadIdx.x;
    int r0 = blockIdx.x * 64;
    int rg = t >> 4, cg = t & 15;
    int cw = t >> 2, ks0 = (t & 3) * 16;

    for (int i = t; i < 64 * 16; i += 256) {
        int row = i / 16, f4 = i % 16;
        *(float4*)&S->xs[row][f4 * 4] = *(const float4*)&g_x1[(r0 + row) * DM + f4 * 4];
    }

    for (int cc = 0; cc < 4; cc++) {
        __syncthreads();
        #pragma unroll
        for (int q = 0; q < 4; q++) {
            float4 wv = *(const float4*)&W1[(cc * 64 + cw) * 64 + ks0 + q * 4];
            S->wb[ks0 + q * 4 + 0][cw] = wv.x;
            S->wb[ks0 + q * 4 + 1][cw] = wv.y;
            S->wb[ks0 + q * 4 + 2][cw] = wv.z;
            S->wb[ks0 + q * 4 + 3][cw] = wv.w;
        }
        __syncthreads();
        float4 acc[4];
        #pragma unroll
        for (int r = 0; r < 4; r++) acc[r] = make_float4(0.f, 0.f, 0.f, 0.f);
        #pragma unroll
        for (int k = 0; k < 64; k += 4) {
            float4 b0 = *(float4*)&S->wb[k + 0][cg * 4];
            float4 b1 = *(float4*)&S->wb[k + 1][cg * 4];
            float4 b2 = *(float4*)&S->wb[k + 2][cg * 4];
            float4 b3 = *(float4*)&S->wb[k + 3][cg * 4];
            #pragma unroll
            for (int r = 0; r < 4; r++) {
                float4 a = *(float4*)&S->xs[rg * 4 + r][k];
                fma4(acc[r], a.x, b0); fma4(acc[r], a.y, b1);
                fma4(acc[r], a.z, b2); fma4(acc[r], a.w, b3);
            }
        }
        float4 bb = *(const float4*)&b1f[cc * 64 + cg * 4];
        #pragma unroll
        for (int r = 0; r < 4; r++) {
            float x0 = acc[r].x + bb.x, x1 = acc[r].y + bb.y;
            float x2 = acc[r].z + bb.z, x3 = acc[r].w + bb.w;
            float4 y;
            y.x = x0 * 0.5f * (1.f + erff(x0 * 0.7071067811865476f));
            y.y = x1 * 0.5f * (1.f + erff(x1 * 0.7071067811865476f));
            y.z = x2 * 0.5f * (1.f + erff(x2 * 0.7071067811865476f));
            y.w = x3 * 0.5f * (1.f + erff(x3 * 0.7071067811865476f));
            *(float4*)&S->ys[rg * 4 + r][cc * 64 + cg * 4] = y;
        }
    }

    float4 acc2[4];
    #pragma unroll
    for (int r = 0; r < 4; r++) acc2[r] = make_float4(0.f, 0.f, 0.f, 0.f);
    for (int kc = 0; kc < 4; kc++) {
        __syncthreads();
        #pragma unroll
        for (int q = 0; q < 4; q++) {
            float4 wv = *(const float4*)&W2[cw * 256 + kc * 64 + ks0 + q * 4];
            S->wb[ks0 + q * 4 + 0][cw] = wv.x;
            S->wb[ks0 + q * 4 + 1][cw] = wv.y;
            S->wb[ks0 + q * 4 + 2][cw] = wv.z;
            S->wb[ks0 + q * 4 + 3][cw] = wv.w;
        }
        __syncthreads();
        #pragma unroll
        for (int k = 0; k < 64; k += 4) {
            float4 b0 = *(float4*)&S->wb[k + 0][cg * 4];
            float4 b1 = *(float4*)&S->wb[k + 1][cg * 4];
            float4 b2 = *(float4*)&S->wb[k + 2][cg * 4];
            float4 b3 = *(float4*)&S->wb[k + 3][cg * 4];
            #pragma unroll
            for (int r = 0; r < 4; r++) {
                float4 a = *(float4*)&S->ys[rg * 4 + r][kc * 64 + k];
                fma4(acc2[r], a.x, b0); fma4(acc2[r], a.y, b1);
                fma4(acc2[r], a.z, b2); fma4(acc2[r], a.w, b3);
            }
        }
    }
    __syncthreads();
    {
        float4 bb = *(const float4*)&b2f[cg * 4];
        #pragma unroll
        for (int r = 0; r < 4; r++) {
            int row = rg * 4 + r;
            S->xs[row][cg * 4 + 0] += acc2[r].x + bb.x;
            S->xs[row][cg * 4 + 1] += acc2[r].y + bb.y;
            S->xs[row][cg * 4 + 2] += acc2[r].z + bb.z;
            S->xs[row][cg * 4 + 3] += acc2[r].w + bb.w;
        }
    }
    __syncthreads();
    int lane = t & 31, w2 = t >> 5;
    #pragma unroll
    for (int rr = 0; rr < 8; rr++) {
        int row = w2 * 8 + rr;
        float v0 = S->xs[row][lane], v1 = S->xs[row][lane + 32];
        float s = v0 + v1;
        #pragma unroll
        for (int o = 16; o; o >>= 1) s += __shfl_xor_sync(0xffffffffu, s, o);
        float mu = s / 64.f;
        float d0 = v0 - mu, d1 = v1 - mu;
        float vv = d0 * d0 + d1 * d1;
        #pragma unroll
        for (int o = 16; o; o >>= 1) vv += __shfl_xor_sync(0xffffffffu, vv, o);
        float inv = rsqrtf(vv / 64.f + 1e-5f);
        g_z[(r0 + row) * DM + lane]      = d0 * inv * g2[lane]      + bb2[lane];
        g_z[(r0 + row) * DM + lane + 32] = d1 * inv * g2[lane + 32] + bb2[lane + 32];
    }
}

// ---------------- final LN ----------------
__global__ void final_ln_kernel(const float* __restrict__ gf, const float* __restrict__ bf) {
    int t = threadIdx.x, lane = t & 31, w = t >> 5;
    int r = blockIdx.x * 8 + w;
    float v0 = g_z[r * DM + lane], v1 = g_z[r * DM + lane + 32];
    float s = v0 + v1;
    #pragma unroll
    for (int o = 16; o; o >>= 1) s += __shfl_xor_sync(0xffffffffu, s, o);
    float mu = s / 64.f;
    float d0 = v0 - mu, d1 = v1 - mu;
    float vv = d0 * d0 + d1 * d1;
    #pragma unroll
    for (int o = 16; o; o >>= 1) vv += __shfl_xor_sync(0xffffffffu, vv, o);
    float inv = rsqrtf(vv / 64.f + 1e-5f);
    g_z[r * DM + lane]      = d0 * inv * gf[lane]      + bf[lane];
    g_z[r * DM + lane + 32] = d1 * inv * gf[lane + 32] + bf[lane + 32];
}

// ---------------- output projection ----------------
__global__ void proj_partial_kernel(const float* __restrict__ outW) {
    int seg = blockIdx.x;
    int bg  = blockIdx.y;
    __shared__ float zc[8][SEG];
    int t = threadIdx.x, lane = t & 31, w = t >> 5;
    int k0 = seg * SEG;
    for (int i = t; i < 8 * SEG; i += 256) {
        int bmo = i / SEG, kk = i % SEG;
        zc[bmo][kk] = g_z[(bg * 8 + bmo) * KTOT + k0 + kk];
    }
    __syncthreads();
    for (int p = w; p < PRED; p += 8) {
        float acc[8] = {0.f, 0.f, 0.f, 0.f, 0.f, 0.f, 0.f, 0.f};
        for (int kk = lane; kk < SEG; kk += 32) {
            float ww = outW[p * KTOT + k0 + kk];
            #pragma unroll
            for (int bmo = 0; bmo < 8; bmo++) acc[bmo] += ww * zc[bmo][kk];
        }
        #pragma unroll
        for (int bmo = 0; bmo < 8; bmo++) {
            #pragma unroll
            for (int o = 16; o; o >>= 1)
                acc[bmo] += __shfl_xor_sync(0xffffffffu, acc[bmo], o);
        }
        if (lane == 0) {
            #pragma unroll
            for (int bmo = 0; bmo < 8; bmo++)
                g_pp[(p * BM + bg * 8 + bmo) * NSEG + seg] = acc[bmo];
        }
    }
}

__global__ void proj_reduce_kernel(const float* __restrict__ outb, float* __restrict__ out) {
    int i = blockIdx.x * 256 + threadIdx.x;
    if (i >= PRED * BM) return;
    int p = i / BM, bm = i % BM;
    float s = outb[p];
    #pragma unroll
    for (int seg = 0; seg < NSEG; seg++) s += g_pp[(p * BM + bm) * NSEG + seg];
    int b = bm / M_, m = bm % M_;
    out[(b * PRED + p) * M_ + m] = s;
}

// ---------------- launch ----------------
extern "C" void kernel_launch(void* const* d_in, const int* in_sizes, int n_in,
                              void* d_out, int out_size) {
    const float* x_enc = (const float*)d_in[0];
    const float* in_W  = (const float*)d_in[4];
    const float* in_b  = (const float*)d_in[5];
    const float* Wq    = (const float*)d_in[6];
    const float* bq    = (const float*)d_in[7];
    const float* Wk    = (const float*)d_in[8];
    const float* bk    = (const float*)d_in[9];
    const float* Wv    = (const float*)d_in[10];
    const float* bv    = (const float*)d_in[11];
    const float* Wo    = (const float*)d_in[12];
    const float* bo    = (const float*)d_in[13];
    const float* c1_W  = (const float*)d_in[14];
    const float* c1_b  = (const float*)d_in[15];
    const float* c2_W  = (const float*)d_in[16];
    const float* c2_b  = (const float*)d_in[17];
    const float* ln1_g = (const float*)d_in[18];
    const float* ln1_b = (const float*)d_in[19];
    const float* ln2_g = (const float*)d_in[20];
    const float* ln2_b = (const float*)d_in[21];
    const float* lnf_g = (const float*)d_in[22];
    const float* lnf_b = (const float*)d_in[23];
    const float* out_W = (const float*)d_in[24];
    const float* out_b = (const float*)d_in[25];
    float* out = (float*)d_out;

    const int smemG = sizeof(SmemG128);
    const int smemF = sizeof(SmemFFN);
    cudaFuncSetAttribute(qkv_kernel,    cudaFuncAttributeMaxDynamicSharedMemorySize, smemG);
    cudaFuncSetAttribute(wo_ln1_kernel, cudaFuncAttributeMaxDynamicSharedMemorySize, smemG);
    cudaFuncSetAttribute(ffn_ln2_kernel,cudaFuncAttributeMaxDynamicSharedMemorySize, smemF);

    patch_embed_kernel<<<NROW / 16, 256>>>(x_enc, in_W, in_b);

    for (int e = 0; e < 2; e++) {
        rand_idx_kernel<<<(NP * UP + 255) / 256, 256>>>(e);
        qkv_kernel<<<dim3(256, 3), 256, smemG>>>(Wq + e * DM * DM, bq + e * DM,
                                                 Wk + e * DM * DM, bk + e * DM,
                                                 Wv + e * DM * DM, bv + e * DM);
        topk_kernel<<<BM * H_, 256>>>();
        vmean_kernel<<<BM, 256>>>();
        bcast_kernel<<<NROW * 16 / 256, 256>>>();
        attn_dense_kernel<<<BM * H_, 256>>>();
        wo_ln1_kernel<<<256, 256, smemG>>>(Wo + e * DM * DM, bo + e * DM,
                                           ln1_g + e * DM, ln1_b + e * DM);
        ffn_ln2_kernel<<<NROW / 64, 256, smemF>>>(c1_W + e * DFF * DM, c1_b + e * DFF,
                                                  c2_W + e * DM * DFF, c2_b + e * DM,
                                                  ln2_g + e * DM, ln2_b + e * DM);
    }

    final_ln_kernel<<<NROW / 8, 256>>>(lnf_g, lnf_b);
    proj_partial_kernel<<<dim3(NSEG, 8), 256>>>(out_W);
    proj_reduce_kernel<<<(PRED * BM + 255) / 256, 256>>>(out_b, out);
}